// round 9
// baseline (speedup 1.0000x reference)
#include <cuda_runtime.h>
#include <cuda_bf16.h>
#include <cuda_fp16.h>
#include <cstdint>

// Problem constants (fixed shapes)
#define N_TOK 8192     // D*H*W
#define BATCH 2
#define CC 96
#define CV 288
#define KIN 320

// fp8 scales
#define QK_SCALE 32.0f     // applied to q and ksum individually
#define V_SCALE  64.0f
#define INV1024  (1.0f / 1024.0f)   // undo QK_SCALE^2 in log2 domain

// ---------------------------------------------------------------------------
// Device scratch
// ---------------------------------------------------------------------------
__device__ __align__(128) __nv_bfloat16 g_Wks[CC * KIN];
__device__ float         g_bks[CC];
__device__ __align__(128) __nv_bfloat16 g_Wv[CV * KIN];
__device__ float         g_bv[CV];
__device__ __align__(128) __nv_bfloat16 g_Wq[CC * CC];
__device__ __align__(128) __nv_bfloat16 g_W6c[CC * CV];
__device__ __align__(128) uint8_t g_ksum[(size_t)BATCH * N_TOK * CC];  // e4m3, [B,N,96], x32, log2e folded
__device__ __align__(128) uint8_t g_q[(size_t)BATCH * N_TOK * CC];     // e4m3, [B,N,96], x32
__device__ __align__(128) uint8_t g_v[(size_t)BATCH * CV * N_TOK];     // e4m3, [B,288,N], x64

// ---------------------------------------------------------------------------
// Helpers
// ---------------------------------------------------------------------------
__device__ __forceinline__ uint32_t ld32bf(const __nv_bfloat16* p) {
    return *reinterpret_cast<const uint32_t*>(p);
}

__device__ __forceinline__ void mma_bf16(float& d0, float& d1, float& d2, float& d3,
                                         uint32_t a0, uint32_t a1, uint32_t a2, uint32_t a3,
                                         uint32_t b0, uint32_t b1)
{
    asm volatile(
        "mma.sync.aligned.m16n8k16.row.col.f32.bf16.bf16.f32 "
        "{%0,%1,%2,%3}, {%4,%5,%6,%7}, {%8,%9}, {%0,%1,%2,%3};\n"
        : "+f"(d0), "+f"(d1), "+f"(d2), "+f"(d3)
        : "r"(a0), "r"(a1), "r"(a2), "r"(a3), "r"(b0), "r"(b1));
}

__device__ __forceinline__ void mma_fp8(float& d0, float& d1, float& d2, float& d3,
                                        uint32_t a0, uint32_t a1, uint32_t a2, uint32_t a3,
                                        uint32_t b0, uint32_t b1)
{
    asm volatile(
        "mma.sync.aligned.m16n8k32.row.col.f32.e4m3.e4m3.f32 "
        "{%0,%1,%2,%3}, {%4,%5,%6,%7}, {%8,%9}, {%0,%1,%2,%3};\n"
        : "+f"(d0), "+f"(d1), "+f"(d2), "+f"(d3)
        : "r"(a0), "r"(a1), "r"(a2), "r"(a3), "r"(b0), "r"(b1));
}

__device__ __forceinline__ void ldsm4(uint32_t addr, uint32_t& r0, uint32_t& r1,
                                      uint32_t& r2, uint32_t& r3)
{
    asm volatile("ldmatrix.sync.aligned.m8n8.x4.shared.b16 {%0,%1,%2,%3}, [%4];\n"
                 : "=r"(r0), "=r"(r1), "=r"(r2), "=r"(r3) : "r"(addr));
}

__device__ __forceinline__ void cp16(uint32_t smem_dst, const void* gsrc)
{
    asm volatile("cp.async.cg.shared.global [%0], [%1], 16;\n"
                 :: "r"(smem_dst), "l"(gsrc));
}
__device__ __forceinline__ void cp_commit() { asm volatile("cp.async.commit_group;\n"); }
__device__ __forceinline__ void cp_wait0()  { asm volatile("cp.async.wait_group 0;\n"); }

// exp2 on two packed fp16 values; inputs fp32 (log2 domain), output f16x2 bits
__device__ __forceinline__ uint32_t ex2_f16x2(float a, float b)
{
    __half2 h = __floats2half2_rn(a, b);
    uint32_t hin = *reinterpret_cast<uint32_t*>(&h);
    uint32_t r;
    asm("ex2.approx.f16x2 %0, %1;" : "=r"(r) : "r"(hin));
    return r;
}

// f16x2 -> e4m3x2 (low f16 -> low byte)
__device__ __forceinline__ uint16_t cvt_e4m3x2_f16x2(uint32_t h2)
{
    uint16_t r;
    asm("cvt.rn.satfinite.e4m3x2.f16x2 %0, %1;" : "=h"(r) : "r"(h2));
    return r;
}

// two f32 -> e4m3x2; 'lo' lands in the low byte
__device__ __forceinline__ uint16_t cvt_e4m3x2_f32(float hi, float lo)
{
    uint16_t r;
    asm("cvt.rn.satfinite.e4m3x2.f32 %0, %1, %2;" : "=h"(r) : "f"(hi), "f"(lo));
    return r;
}

__device__ __forceinline__ void sts16(uint32_t addr, uint16_t v)
{
    asm volatile("st.shared.b16 [%0], %1;" :: "r"(addr), "h"(v) : "memory");
}

// ---------------------------------------------------------------------------
// Prep kernel (R6-proven): 4 threads per output, quad-shfl reduce.
// ---------------------------------------------------------------------------
#define P_O_WKS 0
#define P_O_WV  (CC * KIN)
#define P_O_BKS (P_O_WV + CV * KIN)
#define P_O_BV  (P_O_BKS + CC)
#define P_O_WQ  (P_O_BV + CV)
#define P_O_W6  (P_O_WQ + CC * CC)
#define P_TOT   (P_O_W6 + CC * CV)

__global__ void __launch_bounds__(256) prep_kernel(
    const float* __restrict__ W1, const float* __restrict__ b1,
    const float* __restrict__ W2, const float* __restrict__ b2,
    const float* __restrict__ W3, const float* __restrict__ b3,
    const float* __restrict__ W4, const float* __restrict__ b4,
    const float* __restrict__ W5, const float* __restrict__ W6)
{
    const float LOG2E = 1.44269504088896341f;
    int t = blockIdx.x * blockDim.x + threadIdx.x;
    int e = t >> 2;
    int q = t & 3;
    if (e >= P_TOT) return;
    const uint32_t qmask = 0xFu << (threadIdx.x & 28);

    float acc = 0.f;

    if (e < P_O_WV) {
        int c = e / KIN, i = e % KIN;
        if (i < 128) {
            #pragma unroll 1
            for (int r = 0; r < 3; r++) {
                const float* w3 = W3 + (c + 96 * r) * 288;
                #pragma unroll 4
                for (int j = 48 * q; j < 48 * q + 48; j++) acc += w3[j] * W1[j * 128 + i];
            }
        } else {
            int ih = i - 128;
            #pragma unroll 1
            for (int r = 0; r < 3; r++) {
                const float* w3 = W3 + (c + 96 * r) * 288 + 192;
                #pragma unroll 4
                for (int j = 24 * q; j < 24 * q + 24; j++) acc += w3[j] * W2[j * 192 + ih];
            }
        }
        acc += __shfl_xor_sync(qmask, acc, 1);
        acc += __shfl_xor_sync(qmask, acc, 2);
        if (q == 0) g_Wks[e] = __float2bfloat16(acc * LOG2E);
    } else if (e < P_O_BKS) {
        int u = e - P_O_WV;
        int c = u / KIN, i = u % KIN;
        if (i < 128) {
            const float* w4 = W4 + c * 288;
            #pragma unroll 4
            for (int j = 48 * q; j < 48 * q + 48; j++) acc += w4[j] * W1[j * 128 + i];
        } else {
            int ih = i - 128;
            const float* w4 = W4 + c * 288 + 192;
            #pragma unroll 4
            for (int j = 24 * q; j < 24 * q + 24; j++) acc += w4[j] * W2[j * 192 + ih];
        }
        acc += __shfl_xor_sync(qmask, acc, 1);
        acc += __shfl_xor_sync(qmask, acc, 2);
        if (q == 0) g_Wv[u] = __float2bfloat16(acc);
    } else if (e < P_O_BV) {
        int c = e - P_O_BKS;
        #pragma unroll 1
        for (int r = 0; r < 3; r++) {
            int row = c + 96 * r;
            if (q == 0) acc += b3[row];
            const float* w3 = W3 + row * 288;
            for (int j = 48 * q; j < 48 * q + 48; j++) acc += w3[j] * b1[j];
            for (int j = 24 * q; j < 24 * q + 24; j++) acc += w3[192 + j] * b2[j];
        }
        acc += __shfl_xor_sync(qmask, acc, 1);
        acc += __shfl_xor_sync(qmask, acc, 2);
        if (q == 0) g_bks[c] = acc * LOG2E;
    } else if (e < P_O_WQ) {
        int c = e - P_O_BV;
        if (q == 0) acc += b4[c];
        const float* w4 = W4 + c * 288;
        for (int j = 48 * q; j < 48 * q + 48; j++) acc += w4[j] * b1[j];
        for (int j = 24 * q; j < 24 * q + 24; j++) acc += w4[192 + j] * b2[j];
        acc += __shfl_xor_sync(qmask, acc, 1);
        acc += __shfl_xor_sync(qmask, acc, 2);
        if (q == 0) g_bv[c] = acc;
    } else if (e < P_O_W6) {
        if (q == 0) {
            int u = e - P_O_WQ;
            g_Wq[u] = __float2bfloat16(W5[u]);
        }
    } else {
        if (q == 0) {
            int u = e - P_O_W6;
            g_W6c[u] = __float2bfloat16(W6[u]);
        }
    }
}

// ---------------------------------------------------------------------------
// Projection GEMM body. OUTMODE: 0 = fp8 tok-major [B,N,M], 1 = fp8 ch-major [B,M,N]
// ---------------------------------------------------------------------------
template<int M, int K, int OUTMODE>
__device__ __forceinline__ void proj_body(
    const float* __restrict__ s0, int k0,
    const float* __restrict__ s1, int k1,
    const float* __restrict__ s2,
    const __nv_bfloat16* __restrict__ W,
    const float* __restrict__ bias,
    uint8_t* __restrict__ out, float oscale,
    __nv_bfloat16* sX)
{
    const int tid = threadIdx.x;
    const int warp = tid >> 5;
    const int lane = tid & 31;
    const int t4 = lane >> 2;
    const int tm4 = lane & 3;
    const int b = blockIdx.y;
    const int n0 = blockIdx.x * 64;
    const int rw = warp * 16;

    const float* p0 = s0 + (size_t)b * k0 * N_TOK;
    const float* p1 = s1 + (size_t)b * k1 * N_TOK;
    const float* p2 = s2 + (size_t)b * (K - k0 - k1) * N_TOK;

    constexpr int MT = M / 8;
    float acc[MT][4];
    #pragma unroll
    for (int i = 0; i < MT; i++) { acc[i][0]=0.f; acc[i][1]=0.f; acc[i][2]=0.f; acc[i][3]=0.f; }

    for (int kc = 0; kc < K; kc += 32) {
        #pragma unroll
        for (int it = 0; it < 16; it++) {
            int idx = it * 128 + tid;
            int k = idx >> 6;
            int n = idx & 63;
            int r = kc + k;
            float v;
            if (r < k0)            v = p0[(size_t)r * N_TOK + n0 + n];
            else if (r < k0 + k1)  v = p1[(size_t)(r - k0) * N_TOK + n0 + n];
            else                   v = p2[(size_t)(r - k0 - k1) * N_TOK + n0 + n];
            sX[n * 40 + k] = __float2bfloat16(v);
        }
        __syncthreads();

        #pragma unroll
        for (int ks = 0; ks < 2; ks++) {
            const __nv_bfloat16* qb = sX + (rw + t4) * 40 + ks * 16 + 2 * tm4;
            uint32_t a0 = ld32bf(qb);
            uint32_t a1 = ld32bf(qb + 8 * 40);
            uint32_t a2 = ld32bf(qb + 8);
            uint32_t a3 = ld32bf(qb + 8 * 40 + 8);
            #pragma unroll
            for (int mt = 0; mt < MT; mt++) {
                const __nv_bfloat16* wb = W + (size_t)(mt * 8 + t4) * K + kc + ks * 16 + 2 * tm4;
                uint32_t b0 = ld32bf(wb);
                uint32_t b1 = ld32bf(wb + 8);
                mma_bf16(acc[mt][0], acc[mt][1], acc[mt][2], acc[mt][3],
                         a0, a1, a2, a3, b0, b1);
            }
        }
        __syncthreads();
    }

    int row0 = n0 + rw + t4;
    #pragma unroll
    for (int mt = 0; mt < MT; mt++) {
        int o = mt * 8 + 2 * tm4;
        float bz0 = bias[o], bz1 = bias[o + 1];
        float v0 = (acc[mt][0] + bz0) * oscale;
        float v1 = (acc[mt][1] + bz1) * oscale;
        float v2 = (acc[mt][2] + bz0) * oscale;
        float v3 = (acc[mt][3] + bz1) * oscale;
        if (OUTMODE == 0) {
            uint16_t e0 = cvt_e4m3x2_f32(v1, v0);
            uint16_t e1 = cvt_e4m3x2_f32(v3, v2);
            *reinterpret_cast<uint16_t*>(out + ((size_t)(b * N_TOK + row0)) * M + o) = e0;
            *reinterpret_cast<uint16_t*>(out + ((size_t)(b * N_TOK + row0 + 8)) * M + o) = e1;
        } else {
            uint16_t e0 = cvt_e4m3x2_f32(v1, v0);
            uint16_t e1 = cvt_e4m3x2_f32(v3, v2);
            out[((size_t)(b * M + o)) * N_TOK + row0]         = (uint8_t)(e0 & 0xff);
            out[((size_t)(b * M + o + 1)) * N_TOK + row0]     = (uint8_t)(e0 >> 8);
            out[((size_t)(b * M + o)) * N_TOK + row0 + 8]     = (uint8_t)(e1 & 0xff);
            out[((size_t)(b * M + o + 1)) * N_TOK + row0 + 8] = (uint8_t)(e1 >> 8);
        }
    }
}

// Merged projection kernel: z=0 ksum, z=1 v, z=2 q (all fp8 outputs).
__global__ void __launch_bounds__(128) proj_all_kernel(
    const float* __restrict__ context, const float* __restrict__ h0,
    const float* __restrict__ h1, const float* __restrict__ x,
    const __nv_bfloat16* __restrict__ Wks, const float* __restrict__ bks,
    const __nv_bfloat16* __restrict__ Wv, const float* __restrict__ bv,
    const __nv_bfloat16* __restrict__ Wq, const float* __restrict__ b5,
    uint8_t* __restrict__ ksum_out, uint8_t* __restrict__ v_out,
    uint8_t* __restrict__ q_out)
{
    __shared__ __nv_bfloat16 sX[64 * 40];
    int z = blockIdx.z;
    if (z == 0) {
        proj_body<CC, KIN, 0>(context, 128, h0, 96, h1, Wks, bks, ksum_out, QK_SCALE, sX);
    } else if (z == 1) {
        proj_body<CV, KIN, 1>(context, 128, h0, 96, h1, Wv, bv, v_out, V_SCALE, sX);
    } else {
        proj_body<CC, CC, 0>(x, 96, x, 0, x, Wq, b5, q_out, QK_SCALE, sX);
    }
}

// ---------------------------------------------------------------------------
// FP8 flash attention (R6 structure, e4m3 QMMA m16n8k32).
//   8 warps x 16 Q rows, KV tiles 64, double-buffered cp.async.
//   P' = 2^(S/1024 + 4) in f16 -> e4m3 via per-warp smem staging (syncwarp only).
//   Epilogue: register C-frag -> bf16 A-frag -> W6 HMMA -> +b6 +x (fp32).
// smem (bytes): sQ[128][112] @0 (14336)
//               K bufs 2x[64][112] @14336 (2x7168)
//               V bufs 2x[288][80] @28672 (2x23040)
//               sP per-warp [16][80] @74752 (8x1280) -> total 84992
// ---------------------------------------------------------------------------
#define QT 128
#define KT 64
#define NIT (N_TOK / KT)
#define SQ_STRIDE 112
#define SK_STRIDE 112
#define SV_STRIDE 80
#define SQ_OFF 0
#define SK_OFF 14336
#define K_BUF  7168
#define SV_OFF 28672
#define V_BUF  23040
#define SP_OFF 74752
#define FLASH_SMEM_BYTES 84992

__global__ void __launch_bounds__(256, 1) flash_kernel(
    const uint8_t* __restrict__ qt,    // [B, N, 96] e4m3 x32
    const uint8_t* __restrict__ kst,   // [B, N, 96] e4m3 x32 (log2e folded)
    const uint8_t* __restrict__ vv,    // [B, 288, N] e4m3 x64
    const __nv_bfloat16* __restrict__ W6,    // [96, 288] bf16
    const float* __restrict__ b6,
    const float* __restrict__ x,             // [B, 96, N]
    float* __restrict__ out)                 // [B, 96, N]
{
    extern __shared__ char smraw[];

    const int tid = threadIdx.x;
    const int wid = tid >> 5;
    const int lane = tid & 31;
    const int t4 = lane >> 2;
    const int tm4 = lane & 3;
    const int b = blockIdx.y;
    const int n0 = blockIdx.x * QT;
    const int rw = wid * 16;

    const uint32_t smb = (uint32_t)__cvta_generic_to_shared(smraw);
    const uint32_t sQ_b = smb + SQ_OFF;
    const uint32_t sK_b = smb + SK_OFF;
    const uint32_t sV_b = smb + SV_OFF;
    const uint32_t sP_b = smb + SP_OFF + (uint32_t)wid * 1280;

    const int lg = lane >> 3;
    const int lr = lane & 7;
    const int rsel = (lg & 1) * 8 + lr;
    const int csel16 = (lg >> 1) * 16;     // 16-byte column block
    const uint32_t aAddr0 = sQ_b + (uint32_t)(rw + rsel) * SQ_STRIDE + csel16;
    const uint32_t kAddr0 = sK_b + (uint32_t)rsel * SK_STRIDE + csel16;
    const uint32_t vAddr0 = sV_b + (uint32_t)rsel * SV_STRIDE + csel16;
    const uint32_t pAddrLd = sP_b + (uint32_t)rsel * 80 + csel16;
    const uint32_t pAddrSt = sP_b + (uint32_t)t4 * 80 + 2 * tm4;

    // ---- load Q tile (fp8, 128 x 96 B) ----
    {
        const uint8_t* qsrc = qt + ((size_t)(b * N_TOK + n0)) * 96;
        #pragma unroll
        for (int it = 0; it < 3; it++) {
            int idx = it * 256 + tid;        // 768 chunks of 16B
            int row = idx / 6;
            int c = idx % 6;
            *reinterpret_cast<uint4*>(smraw + SQ_OFF + row * SQ_STRIDE + c * 16) =
                *reinterpret_cast<const uint4*>(qsrc + (size_t)row * 96 + c * 16);
        }
    }

    // ---- async KV tile loader (fp8) ----
    const uint8_t* kbase = kst + ((size_t)b * N_TOK) * 96;
    const uint8_t* vbase = vv + ((size_t)b * CV) * N_TOK;
    auto issue_tile = [&](int mt_i, int buf) {
        const int m0 = mt_i * KT;
        const uint32_t kd = sK_b + (uint32_t)buf * K_BUF;
        const uint32_t vd = sV_b + (uint32_t)buf * V_BUF;
        // K tile: 64 rows x 96 B = 384 chunks
        #pragma unroll
        for (int it = 0; it < 2; it++) {
            int c = it * 256 + tid;
            if (c < 384) {
                int row = c / 6, col = c % 6;
                cp16(kd + (uint32_t)row * SK_STRIDE + col * 16,
                     kbase + (size_t)(m0 + row) * 96 + col * 16);
            }
        }
        // V tile: 288 rows x 64 B = 1152 chunks
        #pragma unroll
        for (int it = 0; it < 5; it++) {
            int c = it * 256 + tid;
            if (c < 1152) {
                int row = c >> 2, col = c & 3;
                cp16(vd + (uint32_t)row * SV_STRIDE + col * 16,
                     vbase + (size_t)row * N_TOK + m0 + col * 16);
            }
        }
        cp_commit();
    };

    float o_[36][4];
    #pragma unroll
    for (int i = 0; i < 36; i++) { o_[i][0]=0.f; o_[i][1]=0.f; o_[i][2]=0.f; o_[i][3]=0.f; }
    float l0 = 0.f, l1 = 0.f;

    issue_tile(0, 0);

    int buf = 0;
    for (int mt_i = 0; mt_i < NIT; mt_i++) {
        cp_wait0();
        __syncthreads();
        if (mt_i + 1 < NIT) issue_tile(mt_i + 1, buf ^ 1);

        const uint32_t kB = kAddr0 + (uint32_t)buf * K_BUF;
        const uint32_t vB = vAddr0 + (uint32_t)buf * V_BUF;

        // ---- S = Q @ K^T (fp8, K=96 in 3 k32 steps) ----
        float s[8][4];
        #pragma unroll
        for (int j = 0; j < 8; j++) { s[j][0]=0.f; s[j][1]=0.f; s[j][2]=0.f; s[j][3]=0.f; }
        #pragma unroll
        for (int kk = 0; kk < 3; kk++) {
            uint32_t a0, a1, a2, a3;
            ldsm4(aAddr0 + kk * 32, a0, a1, a2, a3);
            #pragma unroll
            for (int jj = 0; jj < 4; jj++) {
                uint32_t b00, b01, b10, b11;
                ldsm4(kB + jj * (16 * SK_STRIDE) + kk * 32, b00, b01, b10, b11);
                mma_fp8(s[2*jj][0], s[2*jj][1], s[2*jj][2], s[2*jj][3],
                        a0, a1, a2, a3, b00, b10);
                mma_fp8(s[2*jj+1][0], s[2*jj+1][1], s[2*jj+1][2], s[2*jj+1][3],
                        a0, a1, a2, a3, b01, b11);
            }
        }

        // ---- P' = 2^(S/1024 + 4) in f16; row sums fp32; store e4m3 to sP ----
        __syncwarp();    // prior iter's P ldsm complete before overwrite
        #pragma unroll
        for (int j = 0; j < 8; j++) {
            float t0 = fmaf(s[j][0], INV1024, 4.0f);
            float t1 = fmaf(s[j][1], INV1024, 4.0f);
            float t2 = fmaf(s[j][2], INV1024, 4.0f);
            float t3 = fmaf(s[j][3], INV1024, 4.0f);
            uint32_t h0 = ex2_f16x2(t0, t1);
            uint32_t h1 = ex2_f16x2(t2, t3);
            float2 f01 = __half22float2(*reinterpret_cast<__half2*>(&h0));
            float2 f23 = __half22float2(*reinterpret_cast<__half2*>(&h1));
            l0 += f01.x + f01.y;
            l1 += f23.x + f23.y;
            sts16(pAddrSt + 8 * j, cvt_e4m3x2_f16x2(h0));
            sts16(pAddrSt + 640 + 8 * j, cvt_e4m3x2_f16x2(h1));
        }
        __syncwarp();    // P visible to the whole warp

        // ---- P A-fragments via ldsm (k32 layout for free) ----
        uint32_t pa0[4], pa1[4];
        ldsm4(pAddrLd, pa0[0], pa0[1], pa0[2], pa0[3]);        // tokens 0-31
        ldsm4(pAddrLd + 32, pa1[0], pa1[1], pa1[2], pa1[3]);   // tokens 32-63

        // ---- O += P' @ V'^T (fp8, 2 k32 steps) ----
        #pragma unroll
        for (int g = 0; g < 2; g++) {
            const uint32_t* pag = g ? pa1 : pa0;
            #pragma unroll
            for (int cc = 0; cc < 18; cc++) {
                uint32_t r0, r1, r2, r3;
                ldsm4(vB + cc * (16 * SV_STRIDE) + g * 32, r0, r1, r2, r3);
                mma_fp8(o_[2*cc][0], o_[2*cc][1], o_[2*cc][2], o_[2*cc][3],
                        pag[0], pag[1], pag[2], pag[3], r0, r2);
                mma_fp8(o_[2*cc+1][0], o_[2*cc+1][1], o_[2*cc+1][2], o_[2*cc+1][3],
                        pag[0], pag[1], pag[2], pag[3], r1, r3);
            }
        }
        buf ^= 1;
        __syncthreads();
    }

    // ---- finalize softmax normalization (scales: P'x16, V'x64 -> /64/l') ----
    l0 += __shfl_xor_sync(0xffffffffu, l0, 1);
    l0 += __shfl_xor_sync(0xffffffffu, l0, 2);
    l1 += __shfl_xor_sync(0xffffffffu, l1, 1);
    l1 += __shfl_xor_sync(0xffffffffu, l1, 2);
    float inv0 = 1.f / (64.f * l0);
    float inv1 = 1.f / (64.f * l1);

    // ---- fused epilogue: out = W6 @ res + b6 + x (C-frag == A-frag layout) ----
    float acc[12][4];
    #pragma unroll
    for (int i = 0; i < 12; i++) { acc[i][0]=0.f; acc[i][1]=0.f; acc[i][2]=0.f; acc[i][3]=0.f; }

    #pragma unroll
    for (int ks = 0; ks < 18; ks++) {
        __nv_bfloat162 ta0 = __floats2bfloat162_rn(o_[2*ks][0]*inv0,   o_[2*ks][1]*inv0);
        __nv_bfloat162 ta1 = __floats2bfloat162_rn(o_[2*ks][2]*inv1,   o_[2*ks][3]*inv1);
        __nv_bfloat162 ta2 = __floats2bfloat162_rn(o_[2*ks+1][0]*inv0, o_[2*ks+1][1]*inv0);
        __nv_bfloat162 ta3 = __floats2bfloat162_rn(o_[2*ks+1][2]*inv1, o_[2*ks+1][3]*inv1);
        uint32_t a0 = *reinterpret_cast<uint32_t*>(&ta0);
        uint32_t a1 = *reinterpret_cast<uint32_t*>(&ta1);
        uint32_t a2 = *reinterpret_cast<uint32_t*>(&ta2);
        uint32_t a3 = *reinterpret_cast<uint32_t*>(&ta3);
        #pragma unroll
        for (int mt = 0; mt < 12; mt++) {
            const __nv_bfloat16* wb = W6 + (size_t)(mt * 8 + t4) * CV + ks * 16 + 2 * tm4;
            uint32_t b0 = ld32bf(wb);
            uint32_t b1 = ld32bf(wb + 8);
            mma_bf16(acc[mt][0], acc[mt][1], acc[mt][2], acc[mt][3],
                     a0, a1, a2, a3, b0, b1);
        }
    }

    int n = n0 + rw + t4;
    #pragma unroll
    for (int mt = 0; mt < 12; mt++) {
        int o = mt * 8 + 2 * tm4;
        size_t i00 = ((size_t)(b * CC + o)) * N_TOK + n;
        size_t i01 = i00 + N_TOK;
        out[i00]     = acc[mt][0] + b6[o]     + x[i00];
        out[i01]     = acc[mt][1] + b6[o + 1] + x[i01];
        out[i00 + 8] = acc[mt][2] + b6[o]     + x[i00 + 8];
        out[i01 + 8] = acc[mt][3] + b6[o + 1] + x[i01 + 8];
    }
}

// ---------------------------------------------------------------------------
// Launch
// ---------------------------------------------------------------------------
extern "C" void kernel_launch(void* const* d_in, const int* in_sizes, int n_in,
                              void* d_out, int out_size)
{
    const float* context = (const float*)d_in[0];
    const float* h0 = (const float*)d_in[1];
    const float* h1 = (const float*)d_in[2];
    const float* x  = (const float*)d_in[3];
    const float* W1 = (const float*)d_in[4];
    const float* b1 = (const float*)d_in[5];
    const float* W2 = (const float*)d_in[6];
    const float* b2 = (const float*)d_in[7];
    const float* W3 = (const float*)d_in[8];
    const float* b3 = (const float*)d_in[9];
    const float* W4 = (const float*)d_in[10];
    const float* b4 = (const float*)d_in[11];
    const float* W5 = (const float*)d_in[12];
    const float* b5 = (const float*)d_in[13];
    const float* W6 = (const float*)d_in[14];
    const float* b6 = (const float*)d_in[15];
    float* out = (float*)d_out;

    void *pWks, *pBks, *pWv, *pBv, *pWq, *pW6, *pKsum, *pQ, *pV;
    cudaGetSymbolAddress(&pWks, g_Wks);
    cudaGetSymbolAddress(&pBks, g_bks);
    cudaGetSymbolAddress(&pWv, g_Wv);
    cudaGetSymbolAddress(&pBv, g_bv);
    cudaGetSymbolAddress(&pWq, g_Wq);
    cudaGetSymbolAddress(&pW6, g_W6c);
    cudaGetSymbolAddress(&pKsum, g_ksum);
    cudaGetSymbolAddress(&pQ, g_q);
    cudaGetSymbolAddress(&pV, g_v);

    cudaFuncSetAttribute(flash_kernel, cudaFuncAttributeMaxDynamicSharedMemorySize,
                         FLASH_SMEM_BYTES);

    prep_kernel<<<(P_TOT * 4 + 255) / 256, 256>>>(W1, b1, W2, b2, W3, b3, W4, b4, W5, W6);

    dim3 pgrid(N_TOK / 64, BATCH, 3);
    proj_all_kernel<<<pgrid, 128>>>(
        context, h0, h1, x,
        (const __nv_bfloat16*)pWks, (const float*)pBks,
        (const __nv_bfloat16*)pWv, (const float*)pBv,
        (const __nv_bfloat16*)pWq, b5,
        (uint8_t*)pKsum, (uint8_t*)pV, (uint8_t*)pQ);

    dim3 fgrid(N_TOK / QT, BATCH);
    flash_kernel<<<fgrid, 256, FLASH_SMEM_BYTES>>>(
        (const uint8_t*)pQ, (const uint8_t*)pKsum,
        (const uint8_t*)pV, (const __nv_bfloat16*)pW6,
        b6, x, out);
}

// round 10
// speedup vs baseline: 1.0085x; 1.0085x over previous
#include <cuda_runtime.h>
#include <cuda_bf16.h>
#include <cuda_fp16.h>
#include <cstdint>

// Problem constants (fixed shapes)
#define N_TOK 8192     // D*H*W
#define BATCH 2
#define CC 96
#define CV 288
#define KIN 320

// fp8 scales
#define QK_SCALE 32.0f     // applied to q and ksum individually
#define V_SCALE  64.0f
#define INV1024  (1.0f / 1024.0f)   // undo QK_SCALE^2 in log2 domain

// ---------------------------------------------------------------------------
// Device scratch
// ---------------------------------------------------------------------------
__device__ __align__(128) __nv_bfloat16 g_Wks[CC * KIN];
__device__ float         g_bks[CC];
__device__ __align__(128) __nv_bfloat16 g_Wv[CV * KIN];
__device__ float         g_bv[CV];
__device__ __align__(128) __nv_bfloat16 g_Wq[CC * CC];
__device__ __align__(128) __nv_bfloat16 g_W6c[CC * CV];
__device__ __align__(128) uint8_t g_ksum[(size_t)BATCH * N_TOK * CC];  // e4m3, [B,N,96], x32, log2e folded
__device__ __align__(128) uint8_t g_q[(size_t)BATCH * N_TOK * CC];     // e4m3, [B,N,96], x32
__device__ __align__(128) uint8_t g_v[(size_t)BATCH * CV * N_TOK];     // e4m3, [B,288,N], x64

// ---------------------------------------------------------------------------
// Helpers
// ---------------------------------------------------------------------------
__device__ __forceinline__ uint32_t ld32bf(const __nv_bfloat16* p) {
    return *reinterpret_cast<const uint32_t*>(p);
}

__device__ __forceinline__ void mma_bf16(float& d0, float& d1, float& d2, float& d3,
                                         uint32_t a0, uint32_t a1, uint32_t a2, uint32_t a3,
                                         uint32_t b0, uint32_t b1)
{
    asm volatile(
        "mma.sync.aligned.m16n8k16.row.col.f32.bf16.bf16.f32 "
        "{%0,%1,%2,%3}, {%4,%5,%6,%7}, {%8,%9}, {%0,%1,%2,%3};\n"
        : "+f"(d0), "+f"(d1), "+f"(d2), "+f"(d3)
        : "r"(a0), "r"(a1), "r"(a2), "r"(a3), "r"(b0), "r"(b1));
}

__device__ __forceinline__ void mma_fp8(float& d0, float& d1, float& d2, float& d3,
                                        uint32_t a0, uint32_t a1, uint32_t a2, uint32_t a3,
                                        uint32_t b0, uint32_t b1)
{
    asm volatile(
        "mma.sync.aligned.m16n8k32.row.col.f32.e4m3.e4m3.f32 "
        "{%0,%1,%2,%3}, {%4,%5,%6,%7}, {%8,%9}, {%0,%1,%2,%3};\n"
        : "+f"(d0), "+f"(d1), "+f"(d2), "+f"(d3)
        : "r"(a0), "r"(a1), "r"(a2), "r"(a3), "r"(b0), "r"(b1));
}

__device__ __forceinline__ void ldsm4(uint32_t addr, uint32_t& r0, uint32_t& r1,
                                      uint32_t& r2, uint32_t& r3)
{
    asm volatile("ldmatrix.sync.aligned.m8n8.x4.shared.b16 {%0,%1,%2,%3}, [%4];\n"
                 : "=r"(r0), "=r"(r1), "=r"(r2), "=r"(r3) : "r"(addr));
}

__device__ __forceinline__ void cp16(uint32_t smem_dst, const void* gsrc)
{
    asm volatile("cp.async.cg.shared.global [%0], [%1], 16;\n"
                 :: "r"(smem_dst), "l"(gsrc));
}
__device__ __forceinline__ void cp_commit() { asm volatile("cp.async.commit_group;\n"); }
__device__ __forceinline__ void cp_wait0()  { asm volatile("cp.async.wait_group 0;\n"); }

// exp2 on two packed fp16 values; inputs fp32 (log2 domain), output f16x2 bits
__device__ __forceinline__ uint32_t ex2_f16x2(float a, float b)
{
    __half2 h = __floats2half2_rn(a, b);
    uint32_t hin = *reinterpret_cast<uint32_t*>(&h);
    uint32_t r;
    asm("ex2.approx.f16x2 %0, %1;" : "=r"(r) : "r"(hin));
    return r;
}

// f16x2 -> e4m3x2 (low f16 -> low byte)
__device__ __forceinline__ uint16_t cvt_e4m3x2_f16x2(uint32_t h2)
{
    uint16_t r;
    asm("cvt.rn.satfinite.e4m3x2.f16x2 %0, %1;" : "=h"(r) : "r"(h2));
    return r;
}

// two f32 -> e4m3x2; 'lo' lands in the low byte
__device__ __forceinline__ uint16_t cvt_e4m3x2_f32(float hi, float lo)
{
    uint16_t r;
    asm("cvt.rn.satfinite.e4m3x2.f32 %0, %1, %2;" : "=h"(r) : "f"(hi), "f"(lo));
    return r;
}

__device__ __forceinline__ void sts16(uint32_t addr, uint16_t v)
{
    asm volatile("st.shared.b16 [%0], %1;" :: "r"(addr), "h"(v) : "memory");
}

// ---------------------------------------------------------------------------
// Prep kernel (R6-proven): 4 threads per output, quad-shfl reduce.
// ---------------------------------------------------------------------------
#define P_O_WKS 0
#define P_O_WV  (CC * KIN)
#define P_O_BKS (P_O_WV + CV * KIN)
#define P_O_BV  (P_O_BKS + CC)
#define P_O_WQ  (P_O_BV + CV)
#define P_O_W6  (P_O_WQ + CC * CC)
#define P_TOT   (P_O_W6 + CC * CV)

__global__ void __launch_bounds__(256) prep_kernel(
    const float* __restrict__ W1, const float* __restrict__ b1,
    const float* __restrict__ W2, const float* __restrict__ b2,
    const float* __restrict__ W3, const float* __restrict__ b3,
    const float* __restrict__ W4, const float* __restrict__ b4,
    const float* __restrict__ W5, const float* __restrict__ W6)
{
    const float LOG2E = 1.44269504088896341f;
    int t = blockIdx.x * blockDim.x + threadIdx.x;
    int e = t >> 2;
    int q = t & 3;
    if (e >= P_TOT) return;
    const uint32_t qmask = 0xFu << (threadIdx.x & 28);

    float acc = 0.f;

    if (e < P_O_WV) {
        int c = e / KIN, i = e % KIN;
        if (i < 128) {
            #pragma unroll 1
            for (int r = 0; r < 3; r++) {
                const float* w3 = W3 + (c + 96 * r) * 288;
                #pragma unroll 4
                for (int j = 48 * q; j < 48 * q + 48; j++) acc += w3[j] * W1[j * 128 + i];
            }
        } else {
            int ih = i - 128;
            #pragma unroll 1
            for (int r = 0; r < 3; r++) {
                const float* w3 = W3 + (c + 96 * r) * 288 + 192;
                #pragma unroll 4
                for (int j = 24 * q; j < 24 * q + 24; j++) acc += w3[j] * W2[j * 192 + ih];
            }
        }
        acc += __shfl_xor_sync(qmask, acc, 1);
        acc += __shfl_xor_sync(qmask, acc, 2);
        if (q == 0) g_Wks[e] = __float2bfloat16(acc * LOG2E);
    } else if (e < P_O_BKS) {
        int u = e - P_O_WV;
        int c = u / KIN, i = u % KIN;
        if (i < 128) {
            const float* w4 = W4 + c * 288;
            #pragma unroll 4
            for (int j = 48 * q; j < 48 * q + 48; j++) acc += w4[j] * W1[j * 128 + i];
        } else {
            int ih = i - 128;
            const float* w4 = W4 + c * 288 + 192;
            #pragma unroll 4
            for (int j = 24 * q; j < 24 * q + 24; j++) acc += w4[j] * W2[j * 192 + ih];
        }
        acc += __shfl_xor_sync(qmask, acc, 1);
        acc += __shfl_xor_sync(qmask, acc, 2);
        if (q == 0) g_Wv[u] = __float2bfloat16(acc);
    } else if (e < P_O_BV) {
        int c = e - P_O_BKS;
        #pragma unroll 1
        for (int r = 0; r < 3; r++) {
            int row = c + 96 * r;
            if (q == 0) acc += b3[row];
            const float* w3 = W3 + row * 288;
            for (int j = 48 * q; j < 48 * q + 48; j++) acc += w3[j] * b1[j];
            for (int j = 24 * q; j < 24 * q + 24; j++) acc += w3[192 + j] * b2[j];
        }
        acc += __shfl_xor_sync(qmask, acc, 1);
        acc += __shfl_xor_sync(qmask, acc, 2);
        if (q == 0) g_bks[c] = acc * LOG2E;
    } else if (e < P_O_WQ) {
        int c = e - P_O_BV;
        if (q == 0) acc += b4[c];
        const float* w4 = W4 + c * 288;
        for (int j = 48 * q; j < 48 * q + 48; j++) acc += w4[j] * b1[j];
        for (int j = 24 * q; j < 24 * q + 24; j++) acc += w4[192 + j] * b2[j];
        acc += __shfl_xor_sync(qmask, acc, 1);
        acc += __shfl_xor_sync(qmask, acc, 2);
        if (q == 0) g_bv[c] = acc;
    } else if (e < P_O_W6) {
        if (q == 0) {
            int u = e - P_O_WQ;
            g_Wq[u] = __float2bfloat16(W5[u]);
        }
    } else {
        if (q == 0) {
            int u = e - P_O_W6;
            g_W6c[u] = __float2bfloat16(W6[u]);
        }
    }
}

// ---------------------------------------------------------------------------
// Projection GEMM body. OUTMODE: 0 = fp8 tok-major [B,N,M], 1 = fp8 ch-major [B,M,N]
// ---------------------------------------------------------------------------
template<int M, int K, int OUTMODE>
__device__ __forceinline__ void proj_body(
    const float* __restrict__ s0, int k0,
    const float* __restrict__ s1, int k1,
    const float* __restrict__ s2,
    const __nv_bfloat16* __restrict__ W,
    const float* __restrict__ bias,
    uint8_t* __restrict__ out, float oscale,
    __nv_bfloat16* sX)
{
    const int tid = threadIdx.x;
    const int warp = tid >> 5;
    const int lane = tid & 31;
    const int t4 = lane >> 2;
    const int tm4 = lane & 3;
    const int b = blockIdx.y;
    const int n0 = blockIdx.x * 64;
    const int rw = warp * 16;

    const float* p0 = s0 + (size_t)b * k0 * N_TOK;
    const float* p1 = s1 + (size_t)b * k1 * N_TOK;
    const float* p2 = s2 + (size_t)b * (K - k0 - k1) * N_TOK;

    constexpr int MT = M / 8;
    float acc[MT][4];
    #pragma unroll
    for (int i = 0; i < MT; i++) { acc[i][0]=0.f; acc[i][1]=0.f; acc[i][2]=0.f; acc[i][3]=0.f; }

    for (int kc = 0; kc < K; kc += 32) {
        #pragma unroll
        for (int it = 0; it < 16; it++) {
            int idx = it * 128 + tid;
            int k = idx >> 6;
            int n = idx & 63;
            int r = kc + k;
            float v;
            if (r < k0)            v = p0[(size_t)r * N_TOK + n0 + n];
            else if (r < k0 + k1)  v = p1[(size_t)(r - k0) * N_TOK + n0 + n];
            else                   v = p2[(size_t)(r - k0 - k1) * N_TOK + n0 + n];
            sX[n * 40 + k] = __float2bfloat16(v);
        }
        __syncthreads();

        #pragma unroll
        for (int ks = 0; ks < 2; ks++) {
            const __nv_bfloat16* qb = sX + (rw + t4) * 40 + ks * 16 + 2 * tm4;
            uint32_t a0 = ld32bf(qb);
            uint32_t a1 = ld32bf(qb + 8 * 40);
            uint32_t a2 = ld32bf(qb + 8);
            uint32_t a3 = ld32bf(qb + 8 * 40 + 8);
            #pragma unroll
            for (int mt = 0; mt < MT; mt++) {
                const __nv_bfloat16* wb = W + (size_t)(mt * 8 + t4) * K + kc + ks * 16 + 2 * tm4;
                uint32_t b0 = ld32bf(wb);
                uint32_t b1 = ld32bf(wb + 8);
                mma_bf16(acc[mt][0], acc[mt][1], acc[mt][2], acc[mt][3],
                         a0, a1, a2, a3, b0, b1);
            }
        }
        __syncthreads();
    }

    int row0 = n0 + rw + t4;
    #pragma unroll
    for (int mt = 0; mt < MT; mt++) {
        int o = mt * 8 + 2 * tm4;
        float bz0 = bias[o], bz1 = bias[o + 1];
        float v0 = (acc[mt][0] + bz0) * oscale;
        float v1 = (acc[mt][1] + bz1) * oscale;
        float v2 = (acc[mt][2] + bz0) * oscale;
        float v3 = (acc[mt][3] + bz1) * oscale;
        if (OUTMODE == 0) {
            uint16_t e0 = cvt_e4m3x2_f32(v1, v0);
            uint16_t e1 = cvt_e4m3x2_f32(v3, v2);
            *reinterpret_cast<uint16_t*>(out + ((size_t)(b * N_TOK + row0)) * M + o) = e0;
            *reinterpret_cast<uint16_t*>(out + ((size_t)(b * N_TOK + row0 + 8)) * M + o) = e1;
        } else {
            uint16_t e0 = cvt_e4m3x2_f32(v1, v0);
            uint16_t e1 = cvt_e4m3x2_f32(v3, v2);
            out[((size_t)(b * M + o)) * N_TOK + row0]         = (uint8_t)(e0 & 0xff);
            out[((size_t)(b * M + o + 1)) * N_TOK + row0]     = (uint8_t)(e0 >> 8);
            out[((size_t)(b * M + o)) * N_TOK + row0 + 8]     = (uint8_t)(e1 & 0xff);
            out[((size_t)(b * M + o + 1)) * N_TOK + row0 + 8] = (uint8_t)(e1 >> 8);
        }
    }
}

// Merged projection kernel: z=0 ksum, z=1 v, z=2 q (all fp8 outputs).
__global__ void __launch_bounds__(128) proj_all_kernel(
    const float* __restrict__ context, const float* __restrict__ h0,
    const float* __restrict__ h1, const float* __restrict__ x,
    const __nv_bfloat16* __restrict__ Wks, const float* __restrict__ bks,
    const __nv_bfloat16* __restrict__ Wv, const float* __restrict__ bv,
    const __nv_bfloat16* __restrict__ Wq, const float* __restrict__ b5,
    uint8_t* __restrict__ ksum_out, uint8_t* __restrict__ v_out,
    uint8_t* __restrict__ q_out)
{
    __shared__ __nv_bfloat16 sX[64 * 40];
    int z = blockIdx.z;
    if (z == 0) {
        proj_body<CC, KIN, 0>(context, 128, h0, 96, h1, Wks, bks, ksum_out, QK_SCALE, sX);
    } else if (z == 1) {
        proj_body<CV, KIN, 1>(context, 128, h0, 96, h1, Wv, bv, v_out, V_SCALE, sX);
    } else {
        proj_body<CC, CC, 0>(x, 96, x, 0, x, Wq, b5, q_out, QK_SCALE, sX);
    }
}

// ---------------------------------------------------------------------------
// FP8 flash attention (R6 structure, e4m3 QMMA m16n8k32).
//   8 warps x 16 Q rows, KV tiles 64, double-buffered cp.async.
//   P' = 2^(S/1024 + 4) in f16 -> e4m3 via per-warp smem staging (syncwarp only).
//   Epilogue: register C-frag -> bf16 A-frag -> W6 HMMA -> +b6 +x (fp32).
// smem (bytes): sQ[128][112] @0 (14336)
//               K bufs 2x[64][112] @14336 (2x7168)
//               V bufs 2x[288][80] @28672 (2x23040)
//               sP per-warp [16][80] @74752 (8x1280) -> total 84992
// ---------------------------------------------------------------------------
#define QT 128
#define KT 64
#define NIT (N_TOK / KT)
#define SQ_STRIDE 112
#define SK_STRIDE 112
#define SV_STRIDE 80
#define SQ_OFF 0
#define SK_OFF 14336
#define K_BUF  7168
#define SV_OFF 28672
#define V_BUF  23040
#define SP_OFF 74752
#define FLASH_SMEM_BYTES 84992

__global__ void __launch_bounds__(256, 1) flash_kernel(
    const uint8_t* __restrict__ qt,    // [B, N, 96] e4m3 x32
    const uint8_t* __restrict__ kst,   // [B, N, 96] e4m3 x32 (log2e folded)
    const uint8_t* __restrict__ vv,    // [B, 288, N] e4m3 x64
    const __nv_bfloat16* __restrict__ W6,    // [96, 288] bf16
    const float* __restrict__ b6,
    const float* __restrict__ x,             // [B, 96, N]
    float* __restrict__ out)                 // [B, 96, N]
{
    extern __shared__ char smraw[];

    const int tid = threadIdx.x;
    const int wid = tid >> 5;
    const int lane = tid & 31;
    const int t4 = lane >> 2;
    const int tm4 = lane & 3;
    const int b = blockIdx.y;
    const int n0 = blockIdx.x * QT;
    const int rw = wid * 16;

    const uint32_t smb = (uint32_t)__cvta_generic_to_shared(smraw);
    const uint32_t sQ_b = smb + SQ_OFF;
    const uint32_t sK_b = smb + SK_OFF;
    const uint32_t sV_b = smb + SV_OFF;
    const uint32_t sP_b = smb + SP_OFF + (uint32_t)wid * 1280;

    const int lg = lane >> 3;
    const int lr = lane & 7;
    const int rsel = (lg & 1) * 8 + lr;
    const int csel16 = (lg >> 1) * 16;     // 16-byte column block
    const uint32_t aAddr0 = sQ_b + (uint32_t)(rw + rsel) * SQ_STRIDE + csel16;
    const uint32_t kAddr0 = sK_b + (uint32_t)rsel * SK_STRIDE + csel16;
    const uint32_t vAddr0 = sV_b + (uint32_t)rsel * SV_STRIDE + csel16;
    const uint32_t pAddrLd = sP_b + (uint32_t)rsel * 80 + csel16;
    const uint32_t pAddrSt = sP_b + (uint32_t)t4 * 80 + 2 * tm4;

    // ---- load Q tile (fp8, 128 x 96 B) ----
    {
        const uint8_t* qsrc = qt + ((size_t)(b * N_TOK + n0)) * 96;
        #pragma unroll
        for (int it = 0; it < 3; it++) {
            int idx = it * 256 + tid;        // 768 chunks of 16B
            int row = idx / 6;
            int c = idx % 6;
            *reinterpret_cast<uint4*>(smraw + SQ_OFF + row * SQ_STRIDE + c * 16) =
                *reinterpret_cast<const uint4*>(qsrc + (size_t)row * 96 + c * 16);
        }
    }

    // ---- async KV tile loader (fp8) ----
    const uint8_t* kbase = kst + ((size_t)b * N_TOK) * 96;
    const uint8_t* vbase = vv + ((size_t)b * CV) * N_TOK;
    auto issue_tile = [&](int mt_i, int buf) {
        const int m0 = mt_i * KT;
        const uint32_t kd = sK_b + (uint32_t)buf * K_BUF;
        const uint32_t vd = sV_b + (uint32_t)buf * V_BUF;
        // K tile: 64 rows x 96 B = 384 chunks
        #pragma unroll
        for (int it = 0; it < 2; it++) {
            int c = it * 256 + tid;
            if (c < 384) {
                int row = c / 6, col = c % 6;
                cp16(kd + (uint32_t)row * SK_STRIDE + col * 16,
                     kbase + (size_t)(m0 + row) * 96 + col * 16);
            }
        }
        // V tile: 288 rows x 64 B = 1152 chunks
        #pragma unroll
        for (int it = 0; it < 5; it++) {
            int c = it * 256 + tid;
            if (c < 1152) {
                int row = c >> 2, col = c & 3;
                cp16(vd + (uint32_t)row * SV_STRIDE + col * 16,
                     vbase + (size_t)row * N_TOK + m0 + col * 16);
            }
        }
        cp_commit();
    };

    float o_[36][4];
    #pragma unroll
    for (int i = 0; i < 36; i++) { o_[i][0]=0.f; o_[i][1]=0.f; o_[i][2]=0.f; o_[i][3]=0.f; }
    float l0 = 0.f, l1 = 0.f;

    issue_tile(0, 0);

    int buf = 0;
    for (int mt_i = 0; mt_i < NIT; mt_i++) {
        cp_wait0();
        __syncthreads();
        if (mt_i + 1 < NIT) issue_tile(mt_i + 1, buf ^ 1);

        const uint32_t kB = kAddr0 + (uint32_t)buf * K_BUF;
        const uint32_t vB = vAddr0 + (uint32_t)buf * V_BUF;

        // ---- S = Q @ K^T (fp8, K=96 in 3 k32 steps) ----
        float s[8][4];
        #pragma unroll
        for (int j = 0; j < 8; j++) { s[j][0]=0.f; s[j][1]=0.f; s[j][2]=0.f; s[j][3]=0.f; }
        #pragma unroll
        for (int kk = 0; kk < 3; kk++) {
            uint32_t a0, a1, a2, a3;
            ldsm4(aAddr0 + kk * 32, a0, a1, a2, a3);
            #pragma unroll
            for (int jj = 0; jj < 4; jj++) {
                uint32_t b00, b01, b10, b11;
                ldsm4(kB + jj * (16 * SK_STRIDE) + kk * 32, b00, b01, b10, b11);
                mma_fp8(s[2*jj][0], s[2*jj][1], s[2*jj][2], s[2*jj][3],
                        a0, a1, a2, a3, b00, b10);
                mma_fp8(s[2*jj+1][0], s[2*jj+1][1], s[2*jj+1][2], s[2*jj+1][3],
                        a0, a1, a2, a3, b01, b11);
            }
        }

        // ---- P' = 2^(S/1024 + 4) in f16; row sums fp32; store e4m3 to sP ----
        __syncwarp();    // prior iter's P ldsm complete before overwrite
        #pragma unroll
        for (int j = 0; j < 8; j++) {
            float t0 = fmaf(s[j][0], INV1024, 4.0f);
            float t1 = fmaf(s[j][1], INV1024, 4.0f);
            float t2 = fmaf(s[j][2], INV1024, 4.0f);
            float t3 = fmaf(s[j][3], INV1024, 4.0f);
            uint32_t h0 = ex2_f16x2(t0, t1);
            uint32_t h1 = ex2_f16x2(t2, t3);
            float2 f01 = __half22float2(*reinterpret_cast<__half2*>(&h0));
            float2 f23 = __half22float2(*reinterpret_cast<__half2*>(&h1));
            l0 += f01.x + f01.y;
            l1 += f23.x + f23.y;
            sts16(pAddrSt + 8 * j, cvt_e4m3x2_f16x2(h0));
            sts16(pAddrSt + 640 + 8 * j, cvt_e4m3x2_f16x2(h1));
        }
        __syncwarp();    // P visible to the whole warp

        // ---- P A-fragments via ldsm (k32 layout for free) ----
        uint32_t pa0[4], pa1[4];
        ldsm4(pAddrLd, pa0[0], pa0[1], pa0[2], pa0[3]);        // tokens 0-31
        ldsm4(pAddrLd + 32, pa1[0], pa1[1], pa1[2], pa1[3]);   // tokens 32-63

        // ---- O += P' @ V'^T (fp8, 2 k32 steps) ----
        #pragma unroll
        for (int g = 0; g < 2; g++) {
            const uint32_t* pag = g ? pa1 : pa0;
            #pragma unroll
            for (int cc = 0; cc < 18; cc++) {
                uint32_t r0, r1, r2, r3;
                ldsm4(vB + cc * (16 * SV_STRIDE) + g * 32, r0, r1, r2, r3);
                mma_fp8(o_[2*cc][0], o_[2*cc][1], o_[2*cc][2], o_[2*cc][3],
                        pag[0], pag[1], pag[2], pag[3], r0, r2);
                mma_fp8(o_[2*cc+1][0], o_[2*cc+1][1], o_[2*cc+1][2], o_[2*cc+1][3],
                        pag[0], pag[1], pag[2], pag[3], r1, r3);
            }
        }
        buf ^= 1;
        __syncthreads();
    }

    // ---- finalize softmax normalization (scales: P'x16, V'x64 -> /64/l') ----
    l0 += __shfl_xor_sync(0xffffffffu, l0, 1);
    l0 += __shfl_xor_sync(0xffffffffu, l0, 2);
    l1 += __shfl_xor_sync(0xffffffffu, l1, 1);
    l1 += __shfl_xor_sync(0xffffffffu, l1, 2);
    float inv0 = 1.f / (64.f * l0);
    float inv1 = 1.f / (64.f * l1);

    // ---- fused epilogue: out = W6 @ res + b6 + x (C-frag == A-frag layout) ----
    float acc[12][4];
    #pragma unroll
    for (int i = 0; i < 12; i++) { acc[i][0]=0.f; acc[i][1]=0.f; acc[i][2]=0.f; acc[i][3]=0.f; }

    #pragma unroll
    for (int ks = 0; ks < 18; ks++) {
        __nv_bfloat162 ta0 = __floats2bfloat162_rn(o_[2*ks][0]*inv0,   o_[2*ks][1]*inv0);
        __nv_bfloat162 ta1 = __floats2bfloat162_rn(o_[2*ks][2]*inv1,   o_[2*ks][3]*inv1);
        __nv_bfloat162 ta2 = __floats2bfloat162_rn(o_[2*ks+1][0]*inv0, o_[2*ks+1][1]*inv0);
        __nv_bfloat162 ta3 = __floats2bfloat162_rn(o_[2*ks+1][2]*inv1, o_[2*ks+1][3]*inv1);
        uint32_t a0 = *reinterpret_cast<uint32_t*>(&ta0);
        uint32_t a1 = *reinterpret_cast<uint32_t*>(&ta1);
        uint32_t a2 = *reinterpret_cast<uint32_t*>(&ta2);
        uint32_t a3 = *reinterpret_cast<uint32_t*>(&ta3);
        #pragma unroll
        for (int mt = 0; mt < 12; mt++) {
            const __nv_bfloat16* wb = W6 + (size_t)(mt * 8 + t4) * CV + ks * 16 + 2 * tm4;
            uint32_t b0 = ld32bf(wb);
            uint32_t b1 = ld32bf(wb + 8);
            mma_bf16(acc[mt][0], acc[mt][1], acc[mt][2], acc[mt][3],
                     a0, a1, a2, a3, b0, b1);
        }
    }

    int n = n0 + rw + t4;
    #pragma unroll
    for (int mt = 0; mt < 12; mt++) {
        int o = mt * 8 + 2 * tm4;
        size_t i00 = ((size_t)(b * CC + o)) * N_TOK + n;
        size_t i01 = i00 + N_TOK;
        out[i00]     = acc[mt][0] + b6[o]     + x[i00];
        out[i01]     = acc[mt][1] + b6[o + 1] + x[i01];
        out[i00 + 8] = acc[mt][2] + b6[o]     + x[i00 + 8];
        out[i01 + 8] = acc[mt][3] + b6[o + 1] + x[i01 + 8];
    }
}

// ---------------------------------------------------------------------------
// Launch
// ---------------------------------------------------------------------------
extern "C" void kernel_launch(void* const* d_in, const int* in_sizes, int n_in,
                              void* d_out, int out_size)
{
    const float* context = (const float*)d_in[0];
    const float* h0 = (const float*)d_in[1];
    const float* h1 = (const float*)d_in[2];
    const float* x  = (const float*)d_in[3];
    const float* W1 = (const float*)d_in[4];
    const float* b1 = (const float*)d_in[5];
    const float* W2 = (const float*)d_in[6];
    const float* b2 = (const float*)d_in[7];
    const float* W3 = (const float*)d_in[8];
    const float* b3 = (const float*)d_in[9];
    const float* W4 = (const float*)d_in[10];
    const float* b4 = (const float*)d_in[11];
    const float* W5 = (const float*)d_in[12];
    const float* b5 = (const float*)d_in[13];
    const float* W6 = (const float*)d_in[14];
    const float* b6 = (const float*)d_in[15];
    float* out = (float*)d_out;

    void *pWks, *pBks, *pWv, *pBv, *pWq, *pW6, *pKsum, *pQ, *pV;
    cudaGetSymbolAddress(&pWks, g_Wks);
    cudaGetSymbolAddress(&pBks, g_bks);
    cudaGetSymbolAddress(&pWv, g_Wv);
    cudaGetSymbolAddress(&pBv, g_bv);
    cudaGetSymbolAddress(&pWq, g_Wq);
    cudaGetSymbolAddress(&pW6, g_W6c);
    cudaGetSymbolAddress(&pKsum, g_ksum);
    cudaGetSymbolAddress(&pQ, g_q);
    cudaGetSymbolAddress(&pV, g_v);

    cudaFuncSetAttribute(flash_kernel, cudaFuncAttributeMaxDynamicSharedMemorySize,
                         FLASH_SMEM_BYTES);

    prep_kernel<<<(P_TOT * 4 + 255) / 256, 256>>>(W1, b1, W2, b2, W3, b3, W4, b4, W5, W6);

    dim3 pgrid(N_TOK / 64, BATCH, 3);
    proj_all_kernel<<<pgrid, 128>>>(
        context, h0, h1, x,
        (const __nv_bfloat16*)pWks, (const float*)pBks,
        (const __nv_bfloat16*)pWv, (const float*)pBv,
        (const __nv_bfloat16*)pWq, b5,
        (uint8_t*)pKsum, (uint8_t*)pV, (uint8_t*)pQ);

    dim3 fgrid(N_TOK / QT, BATCH);
    flash_kernel<<<fgrid, 256, FLASH_SMEM_BYTES>>>(
        (const uint8_t*)pQ, (const uint8_t*)pKsum,
        (const uint8_t*)pV, (const __nv_bfloat16*)pW6,
        b6, x, out);
}

// round 11
// speedup vs baseline: 2.1189x; 2.1010x over previous
#include <cuda_runtime.h>
#include <cuda_bf16.h>
#include <cuda_fp16.h>
#include <cstdint>

// Problem constants (fixed shapes)
#define N_TOK 8192     // D*H*W
#define BATCH 2
#define CC 96
#define CV 288
#define KIN 320

// ---------------------------------------------------------------------------
// Device scratch
// ---------------------------------------------------------------------------
__device__ float g_W64[CC * CV];     // W6 @ W4  (fp32, stage-A scratch)
__device__ float g_bvc[CV];          // combined v bias (fp32, stage-A scratch)

__device__ __align__(128) __nv_bfloat16 g_Wks[CC * KIN];
__device__ float         g_bks[CC];
__device__ __align__(128) __nv_bfloat16 g_Wv6[CC * KIN];   // (W6@W4) @ [W1;W2]
__device__ float         g_bv6[CC];
__device__ __align__(128) __nv_bfloat16 g_Wq[CC * CC];
__device__ __align__(128) __nv_bfloat16 g_ksum[(size_t)BATCH * N_TOK * CC];  // [B,N,96] bf16 (log2e)
__device__ __align__(128) __nv_bfloat16 g_q[(size_t)BATCH * N_TOK * CC];     // [B,N,96] bf16
__device__ __align__(128) __half        g_v6[(size_t)BATCH * CC * N_TOK];    // [B,96,N] fp16

// ---------------------------------------------------------------------------
// Helpers
// ---------------------------------------------------------------------------
__device__ __forceinline__ uint32_t ld32bf(const __nv_bfloat16* p) {
    return *reinterpret_cast<const uint32_t*>(p);
}

__device__ __forceinline__ void mma_bf16(float& d0, float& d1, float& d2, float& d3,
                                         uint32_t a0, uint32_t a1, uint32_t a2, uint32_t a3,
                                         uint32_t b0, uint32_t b1)
{
    asm volatile(
        "mma.sync.aligned.m16n8k16.row.col.f32.bf16.bf16.f32 "
        "{%0,%1,%2,%3}, {%4,%5,%6,%7}, {%8,%9}, {%0,%1,%2,%3};\n"
        : "+f"(d0), "+f"(d1), "+f"(d2), "+f"(d3)
        : "r"(a0), "r"(a1), "r"(a2), "r"(a3), "r"(b0), "r"(b1));
}

__device__ __forceinline__ void mma_f16(float& d0, float& d1, float& d2, float& d3,
                                        uint32_t a0, uint32_t a1, uint32_t a2, uint32_t a3,
                                        uint32_t b0, uint32_t b1)
{
    asm volatile(
        "mma.sync.aligned.m16n8k16.row.col.f32.f16.f16.f32 "
        "{%0,%1,%2,%3}, {%4,%5,%6,%7}, {%8,%9}, {%0,%1,%2,%3};\n"
        : "+f"(d0), "+f"(d1), "+f"(d2), "+f"(d3)
        : "r"(a0), "r"(a1), "r"(a2), "r"(a3), "r"(b0), "r"(b1));
}

__device__ __forceinline__ void ldsm4(uint32_t addr, uint32_t& r0, uint32_t& r1,
                                      uint32_t& r2, uint32_t& r3)
{
    asm volatile("ldmatrix.sync.aligned.m8n8.x4.shared.b16 {%0,%1,%2,%3}, [%4];\n"
                 : "=r"(r0), "=r"(r1), "=r"(r2), "=r"(r3) : "r"(addr));
}

__device__ __forceinline__ void cp16(uint32_t smem_dst, const void* gsrc)
{
    asm volatile("cp.async.cg.shared.global [%0], [%1], 16;\n"
                 :: "r"(smem_dst), "l"(gsrc));
}
__device__ __forceinline__ void cp_commit() { asm volatile("cp.async.commit_group;\n"); }
__device__ __forceinline__ void cp_wait0()  { asm volatile("cp.async.wait_group 0;\n"); }

// exp2 on two packed fp16; inputs fp32 (log2 domain), output f16x2 bits
__device__ __forceinline__ uint32_t ex2_f16x2(float a, float b)
{
    __half2 h = __floats2half2_rn(a, b);
    uint32_t hin = *reinterpret_cast<uint32_t*>(&h);
    uint32_t r;
    asm("ex2.approx.f16x2 %0, %1;" : "=r"(r) : "r"(hin));
    return r;
}

// ---------------------------------------------------------------------------
// Prep stage A: W64 = W6 @ W4, bvc = b4 + W4a@b1 + W4b@b2
// 4 threads per output, quad-shfl reduce.
// ---------------------------------------------------------------------------
#define PA_TOT (CC * CV + CV)

__global__ void __launch_bounds__(256) prep_a_kernel(
    const float* __restrict__ W1, const float* __restrict__ b1,
    const float* __restrict__ W2, const float* __restrict__ b2,
    const float* __restrict__ W4, const float* __restrict__ b4,
    const float* __restrict__ W6)
{
    int t = blockIdx.x * blockDim.x + threadIdx.x;
    int e = t >> 2;
    int q = t & 3;
    if (e >= PA_TOT) return;
    const uint32_t qmask = 0xFu << (threadIdx.x & 28);

    float acc = 0.f;
    if (e < CC * CV) {
        int o = e / CV, j = e % CV;
        const float* w6 = W6 + o * CV;
        #pragma unroll 4
        for (int c = 72 * q; c < 72 * q + 72; c++) acc += w6[c] * W4[c * CV + j];
        acc += __shfl_xor_sync(qmask, acc, 1);
        acc += __shfl_xor_sync(qmask, acc, 2);
        if (q == 0) g_W64[e] = acc;
    } else {
        int c = e - CC * CV;
        const float* w4 = W4 + c * CV;
        if (q == 0) acc += b4[c];
        for (int j = 48 * q; j < 48 * q + 48; j++) acc += w4[j] * b1[j];
        for (int j = 24 * q; j < 24 * q + 24; j++) acc += w4[192 + j] * b2[j];
        acc += __shfl_xor_sync(qmask, acc, 1);
        acc += __shfl_xor_sync(qmask, acc, 2);
        if (q == 0) g_bvc[c] = acc;
    }
}

// ---------------------------------------------------------------------------
// Prep stage B: Wks (log2e), bks, Wv6 = W64 @ [W1;W2], bv6 = W6 @ bvc, Wq
// ---------------------------------------------------------------------------
#define PB_O_WKS 0
#define PB_O_BKS (CC * KIN)                  // 30720
#define PB_O_WV6 (PB_O_BKS + CC)             // 30816
#define PB_O_BV6 (PB_O_WV6 + CC * KIN)       // 61536
#define PB_O_WQ  (PB_O_BV6 + CC)             // 61632
#define PB_TOT   (PB_O_WQ + CC * CC)         // 70848

__global__ void __launch_bounds__(256) prep_b_kernel(
    const float* __restrict__ W1, const float* __restrict__ b1,
    const float* __restrict__ W2, const float* __restrict__ b2,
    const float* __restrict__ W3, const float* __restrict__ b3,
    const float* __restrict__ W5, const float* __restrict__ W6)
{
    const float LOG2E = 1.44269504088896341f;
    int t = blockIdx.x * blockDim.x + threadIdx.x;
    int e = t >> 2;
    int q = t & 3;
    if (e >= PB_TOT) return;
    const uint32_t qmask = 0xFu << (threadIdx.x & 28);

    float acc = 0.f;

    if (e < PB_O_BKS) {
        int c = e / KIN, i = e % KIN;
        if (i < 128) {
            #pragma unroll 1
            for (int r = 0; r < 3; r++) {
                const float* w3 = W3 + (c + 96 * r) * 288;
                #pragma unroll 4
                for (int j = 48 * q; j < 48 * q + 48; j++) acc += w3[j] * W1[j * 128 + i];
            }
        } else {
            int ih = i - 128;
            #pragma unroll 1
            for (int r = 0; r < 3; r++) {
                const float* w3 = W3 + (c + 96 * r) * 288 + 192;
                #pragma unroll 4
                for (int j = 24 * q; j < 24 * q + 24; j++) acc += w3[j] * W2[j * 192 + ih];
            }
        }
        acc += __shfl_xor_sync(qmask, acc, 1);
        acc += __shfl_xor_sync(qmask, acc, 2);
        if (q == 0) g_Wks[e] = __float2bfloat16(acc * LOG2E);
    } else if (e < PB_O_WV6) {
        int c = e - PB_O_BKS;
        #pragma unroll 1
        for (int r = 0; r < 3; r++) {
            int row = c + 96 * r;
            if (q == 0) acc += b3[row];
            const float* w3 = W3 + row * 288;
            for (int j = 48 * q; j < 48 * q + 48; j++) acc += w3[j] * b1[j];
            for (int j = 24 * q; j < 24 * q + 24; j++) acc += w3[192 + j] * b2[j];
        }
        acc += __shfl_xor_sync(qmask, acc, 1);
        acc += __shfl_xor_sync(qmask, acc, 2);
        if (q == 0) g_bks[c] = acc * LOG2E;
    } else if (e < PB_O_BV6) {
        int u = e - PB_O_WV6;
        int o = u / KIN, i = u % KIN;
        if (i < 128) {
            const float* w = g_W64 + o * CV;
            #pragma unroll 4
            for (int j = 48 * q; j < 48 * q + 48; j++) acc += w[j] * W1[j * 128 + i];
        } else {
            int ih = i - 128;
            const float* w = g_W64 + o * CV + 192;
            #pragma unroll 4
            for (int j = 24 * q; j < 24 * q + 24; j++) acc += w[j] * W2[j * 192 + ih];
        }
        acc += __shfl_xor_sync(qmask, acc, 1);
        acc += __shfl_xor_sync(qmask, acc, 2);
        if (q == 0) g_Wv6[u] = __float2bfloat16(acc);
    } else if (e < PB_O_WQ) {
        int o = e - PB_O_BV6;
        const float* w6 = W6 + o * CV;
        #pragma unroll 4
        for (int c = 72 * q; c < 72 * q + 72; c++) acc += w6[c] * g_bvc[c];
        acc += __shfl_xor_sync(qmask, acc, 1);
        acc += __shfl_xor_sync(qmask, acc, 2);
        if (q == 0) g_bv6[o] = acc;
    } else {
        if (q == 0) {
            int u = e - PB_O_WQ;
            g_Wq[u] = __float2bfloat16(W5[u]);
        }
    }
}

// ---------------------------------------------------------------------------
// Projection GEMM body. OUTMODE: 0 = bf16 tok-major [B,N,M], 1 = fp16 ch-major [B,M,N]
// ---------------------------------------------------------------------------
template<int M, int K, int OUTMODE>
__device__ __forceinline__ void proj_body(
    const float* __restrict__ s0, int k0,
    const float* __restrict__ s1, int k1,
    const float* __restrict__ s2,
    const __nv_bfloat16* __restrict__ W,
    const float* __restrict__ bias,
    void* __restrict__ outv,
    __nv_bfloat16* sX)
{
    const int tid = threadIdx.x;
    const int warp = tid >> 5;
    const int lane = tid & 31;
    const int t4 = lane >> 2;
    const int tm4 = lane & 3;
    const int b = blockIdx.y;
    const int n0 = blockIdx.x * 64;
    const int rw = warp * 16;

    const float* p0 = s0 + (size_t)b * k0 * N_TOK;
    const float* p1 = s1 + (size_t)b * k1 * N_TOK;
    const float* p2 = s2 + (size_t)b * (K - k0 - k1) * N_TOK;

    constexpr int MT = M / 8;
    float acc[MT][4];
    #pragma unroll
    for (int i = 0; i < MT; i++) { acc[i][0]=0.f; acc[i][1]=0.f; acc[i][2]=0.f; acc[i][3]=0.f; }

    for (int kc = 0; kc < K; kc += 32) {
        #pragma unroll
        for (int it = 0; it < 16; it++) {
            int idx = it * 128 + tid;
            int k = idx >> 6;
            int n = idx & 63;
            int r = kc + k;
            float v;
            if (r < k0)            v = p0[(size_t)r * N_TOK + n0 + n];
            else if (r < k0 + k1)  v = p1[(size_t)(r - k0) * N_TOK + n0 + n];
            else                   v = p2[(size_t)(r - k0 - k1) * N_TOK + n0 + n];
            sX[n * 40 + k] = __float2bfloat16(v);
        }
        __syncthreads();

        #pragma unroll
        for (int ks = 0; ks < 2; ks++) {
            const __nv_bfloat16* qb = sX + (rw + t4) * 40 + ks * 16 + 2 * tm4;
            uint32_t a0 = ld32bf(qb);
            uint32_t a1 = ld32bf(qb + 8 * 40);
            uint32_t a2 = ld32bf(qb + 8);
            uint32_t a3 = ld32bf(qb + 8 * 40 + 8);
            #pragma unroll
            for (int mt = 0; mt < MT; mt++) {
                const __nv_bfloat16* wb = W + (size_t)(mt * 8 + t4) * K + kc + ks * 16 + 2 * tm4;
                uint32_t b0 = ld32bf(wb);
                uint32_t b1 = ld32bf(wb + 8);
                mma_bf16(acc[mt][0], acc[mt][1], acc[mt][2], acc[mt][3],
                         a0, a1, a2, a3, b0, b1);
            }
        }
        __syncthreads();
    }

    int row0 = n0 + rw + t4;
    #pragma unroll
    for (int mt = 0; mt < MT; mt++) {
        int o = mt * 8 + 2 * tm4;
        float bz0 = bias[o], bz1 = bias[o + 1];
        float v0 = acc[mt][0] + bz0;
        float v1 = acc[mt][1] + bz1;
        float v2 = acc[mt][2] + bz0;
        float v3 = acc[mt][3] + bz1;
        if (OUTMODE == 0) {
            __nv_bfloat16* out = (__nv_bfloat16*)outv;
            *reinterpret_cast<__nv_bfloat162*>(out + ((size_t)(b * N_TOK + row0)) * M + o) =
                __floats2bfloat162_rn(v0, v1);
            *reinterpret_cast<__nv_bfloat162*>(out + ((size_t)(b * N_TOK + row0 + 8)) * M + o) =
                __floats2bfloat162_rn(v2, v3);
        } else {
            __half* out = (__half*)outv;
            out[((size_t)(b * M + o)) * N_TOK + row0]         = __float2half(v0);
            out[((size_t)(b * M + o + 1)) * N_TOK + row0]     = __float2half(v1);
            out[((size_t)(b * M + o)) * N_TOK + row0 + 8]     = __float2half(v2);
            out[((size_t)(b * M + o + 1)) * N_TOK + row0 + 8] = __float2half(v3);
        }
    }
}

// Merged projection kernel: z=0 ksum, z=1 v6 (fp16 ch-major), z=2 q.
__global__ void __launch_bounds__(128) proj_all_kernel(
    const float* __restrict__ context, const float* __restrict__ h0,
    const float* __restrict__ h1, const float* __restrict__ x,
    const __nv_bfloat16* __restrict__ Wks, const float* __restrict__ bks,
    const __nv_bfloat16* __restrict__ Wv6, const float* __restrict__ bv6,
    const __nv_bfloat16* __restrict__ Wq, const float* __restrict__ b5,
    __nv_bfloat16* __restrict__ ksum_out, __half* __restrict__ v6_out,
    __nv_bfloat16* __restrict__ q_out)
{
    __shared__ __nv_bfloat16 sX[64 * 40];
    int z = blockIdx.z;
    if (z == 0) {
        proj_body<CC, KIN, 0>(context, 128, h0, 96, h1, Wks, bks, ksum_out, sX);
    } else if (z == 1) {
        proj_body<CC, KIN, 1>(context, 128, h0, 96, h1, Wv6, bv6, v6_out, sX);
    } else {
        proj_body<CC, CC, 0>(x, 96, x, 0, x, Wq, b5, q_out, sX);
    }
}

// ---------------------------------------------------------------------------
// Flash attention with pre-projected V6 (96 channels).
//   R6-proven structure: 8 warps x 16 Q rows, KV tiles 64, double-buffered
//   cp.async, bf16 QK, fp16 P/V6, ex2.f16x2 softmax, no mid-iter syncs.
//   Epilogue: out = O/l + b6 + x directly (no W6 GEMM - folded into V6).
// smem: sQ[128][104] @0 (26,624) | K bufs 2x[64][104] @26,624 (2x13,312)
//       V6 bufs 2x[96][72] fp16 @53,248 (2x13,824) -> total 80,896 B
// ---------------------------------------------------------------------------
#define QT 128
#define KT 64
#define NIT (N_TOK / KT)
#define SQ_ELEMS (128 * 104)
#define SK_ELEMS (64 * 104)
#define SV_ELEMS (96 * 72)
#define FLASH_SMEM_BYTES ((SQ_ELEMS + 2 * SK_ELEMS + 2 * SV_ELEMS) * 2)  // 80,896

__global__ void __launch_bounds__(256, 1) flash_kernel(
    const __nv_bfloat16* __restrict__ qt,    // [B, N, 96]
    const __nv_bfloat16* __restrict__ kst,   // [B, N, 96] (log2e-scaled)
    const __half* __restrict__ v6,           // [B, 96, N] fp16
    const float* __restrict__ b6,
    const float* __restrict__ x,             // [B, 96, N]
    float* __restrict__ out)                 // [B, 96, N]
{
    extern __shared__ __nv_bfloat16 smem[];
    __nv_bfloat16* sQ = smem;

    const int tid = threadIdx.x;
    const int warp = tid >> 5;
    const int lane = tid & 31;
    const int t4 = lane >> 2;
    const int tm4 = lane & 3;
    const int b = blockIdx.y;
    const int n0 = blockIdx.x * QT;
    const int rw = warp * 16;

    const uint32_t smem_b = (uint32_t)__cvta_generic_to_shared(smem);
    const uint32_t sQ_b = smem_b;
    const uint32_t sK_b = smem_b + SQ_ELEMS * 2;
    const uint32_t sV_b = smem_b + (SQ_ELEMS + 2 * SK_ELEMS) * 2;

    const int lg = lane >> 3;
    const int lr = lane & 7;
    const int rsel = (lg & 1) * 8 + lr;
    const int csel = (lg >> 1) * 8;
    const uint32_t aAddr0 = sQ_b + ((rw + rsel) * 104 + csel) * 2;
    const uint32_t kAddr0 = sK_b + (rsel * 104 + csel) * 2;
    const uint32_t vAddr0 = sV_b + (rsel * 72 + csel) * 2;

    // ---- load Q tile ----
    {
        const __nv_bfloat16* qsrc = qt + ((size_t)(b * N_TOK + n0)) * 96;
        #pragma unroll
        for (int it = 0; it < 6; it++) {
            int idx = it * 256 + tid;
            int row = idx / 12;
            int c8 = idx % 12;
            *reinterpret_cast<uint4*>(sQ + row * 104 + c8 * 8) =
                *reinterpret_cast<const uint4*>(qsrc + (size_t)row * 96 + c8 * 8);
        }
    }

    // ---- async tile loader ----
    const __nv_bfloat16* kbase = kst + ((size_t)b * N_TOK) * 96;
    const __half* vbase = v6 + ((size_t)b * CC) * N_TOK;
    auto issue_tile = [&](int mt_i, int buf) {
        const int m0 = mt_i * KT;
        // K tile: 64 rows x 96 cols = 768 16B chunks
        #pragma unroll
        for (int it = 0; it < 3; it++) {
            int c = it * 256 + tid;
            int row = c / 12, col = c % 12;
            cp16(sK_b + (buf * SK_ELEMS + row * 104 + col * 8) * 2,
                 kbase + (size_t)(m0 + row) * 96 + col * 8);
        }
        // V6 tile: 96 rows x 64 cols = 768 16B chunks
        #pragma unroll
        for (int it = 0; it < 3; it++) {
            int c = it * 256 + tid;
            int row = c >> 3, col = c & 7;
            cp16(sV_b + (buf * SV_ELEMS + row * 72 + col * 8) * 2,
                 vbase + (size_t)row * N_TOK + m0 + col * 8);
        }
        cp_commit();
    };

    float o_[12][4];
    #pragma unroll
    for (int i = 0; i < 12; i++) { o_[i][0]=0.f; o_[i][1]=0.f; o_[i][2]=0.f; o_[i][3]=0.f; }
    float l0 = 0.f, l1 = 0.f;

    issue_tile(0, 0);

    int buf = 0;
    for (int mt_i = 0; mt_i < NIT; mt_i++) {
        cp_wait0();
        __syncthreads();
        if (mt_i + 1 < NIT) issue_tile(mt_i + 1, buf ^ 1);

        const uint32_t kB = kAddr0 + buf * (SK_ELEMS * 2);
        const uint32_t vB = vAddr0 + buf * (SV_ELEMS * 2);

        // ---- S = Q @ K^T (bf16) ----
        float s[8][4];
        #pragma unroll
        for (int j = 0; j < 8; j++) { s[j][0]=0.f; s[j][1]=0.f; s[j][2]=0.f; s[j][3]=0.f; }
        #pragma unroll
        for (int kk = 0; kk < 6; kk++) {
            uint32_t a0, a1, a2, a3;
            ldsm4(aAddr0 + kk * 32, a0, a1, a2, a3);
            #pragma unroll
            for (int jj = 0; jj < 4; jj++) {
                uint32_t b00, b01, b10, b11;
                ldsm4(kB + jj * (16 * 208) + kk * 32, b00, b01, b10, b11);
                mma_bf16(s[2*jj][0], s[2*jj][1], s[2*jj][2], s[2*jj][3],
                         a0, a1, a2, a3, b00, b10);
                mma_bf16(s[2*jj+1][0], s[2*jj+1][1], s[2*jj+1][2], s[2*jj+1][3],
                         a0, a1, a2, a3, b01, b11);
            }
        }

        // ---- P = exp2(S) via f16x2 MUFU; fp32 row sums; P fp16 in regs ----
        uint32_t pa[4][4];
        #pragma unroll
        for (int j = 0; j < 8; j++) {
            uint32_t e01 = ex2_f16x2(s[j][0], s[j][1]);
            uint32_t e23 = ex2_f16x2(s[j][2], s[j][3]);
            float2 f01 = __half22float2(*reinterpret_cast<__half2*>(&e01));
            float2 f23 = __half22float2(*reinterpret_cast<__half2*>(&e23));
            l0 += f01.x + f01.y;
            l1 += f23.x + f23.y;
            pa[j >> 1][(j & 1) * 2]     = e01;
            pa[j >> 1][(j & 1) * 2 + 1] = e23;
        }

        // ---- O += P @ V6^T (fp16 inputs, fp32 accum; 96 channels) ----
        #pragma unroll
        for (int g = 0; g < 4; g++) {
            #pragma unroll
            for (int cc = 0; cc < 6; cc++) {
                uint32_t r0, r1, r2, r3;
                ldsm4(vB + cc * (16 * 144) + g * 32, r0, r1, r2, r3);
                mma_f16(o_[2*cc][0], o_[2*cc][1], o_[2*cc][2], o_[2*cc][3],
                        pa[g][0], pa[g][1], pa[g][2], pa[g][3], r0, r2);
                mma_f16(o_[2*cc+1][0], o_[2*cc+1][1], o_[2*cc+1][2], o_[2*cc+1][3],
                        pa[g][0], pa[g][1], pa[g][2], pa[g][3], r1, r3);
            }
        }
        buf ^= 1;
        __syncthreads();
    }

    // ---- finalize softmax normalization ----
    l0 += __shfl_xor_sync(0xffffffffu, l0, 1);
    l0 += __shfl_xor_sync(0xffffffffu, l0, 2);
    l1 += __shfl_xor_sync(0xffffffffu, l1, 1);
    l1 += __shfl_xor_sync(0xffffffffu, l1, 2);
    float inv0 = 1.f / l0;
    float inv1 = 1.f / l1;

    // ---- epilogue: out = O/l + b6 + x (W6 already folded into V6) ----
    int n = n0 + rw + t4;
    #pragma unroll
    for (int mt = 0; mt < 12; mt++) {
        int o = mt * 8 + 2 * tm4;
        size_t i00 = ((size_t)(b * CC + o)) * N_TOK + n;
        size_t i01 = i00 + N_TOK;
        out[i00]     = o_[mt][0] * inv0 + b6[o]     + x[i00];
        out[i01]     = o_[mt][1] * inv0 + b6[o + 1] + x[i01];
        out[i00 + 8] = o_[mt][2] * inv1 + b6[o]     + x[i00 + 8];
        out[i01 + 8] = o_[mt][3] * inv1 + b6[o + 1] + x[i01 + 8];
    }
}

// ---------------------------------------------------------------------------
// Launch
// ---------------------------------------------------------------------------
extern "C" void kernel_launch(void* const* d_in, const int* in_sizes, int n_in,
                              void* d_out, int out_size)
{
    const float* context = (const float*)d_in[0];
    const float* h0 = (const float*)d_in[1];
    const float* h1 = (const float*)d_in[2];
    const float* x  = (const float*)d_in[3];
    const float* W1 = (const float*)d_in[4];
    const float* b1 = (const float*)d_in[5];
    const float* W2 = (const float*)d_in[6];
    const float* b2 = (const float*)d_in[7];
    const float* W3 = (const float*)d_in[8];
    const float* b3 = (const float*)d_in[9];
    const float* W4 = (const float*)d_in[10];
    const float* b4 = (const float*)d_in[11];
    const float* W5 = (const float*)d_in[12];
    const float* b5 = (const float*)d_in[13];
    const float* W6 = (const float*)d_in[14];
    const float* b6 = (const float*)d_in[15];
    float* out = (float*)d_out;

    void *pWks, *pBks, *pWv6, *pBv6, *pWq, *pKsum, *pQ, *pV6;
    cudaGetSymbolAddress(&pWks, g_Wks);
    cudaGetSymbolAddress(&pBks, g_bks);
    cudaGetSymbolAddress(&pWv6, g_Wv6);
    cudaGetSymbolAddress(&pBv6, g_bv6);
    cudaGetSymbolAddress(&pWq, g_Wq);
    cudaGetSymbolAddress(&pKsum, g_ksum);
    cudaGetSymbolAddress(&pQ, g_q);
    cudaGetSymbolAddress(&pV6, g_v6);

    cudaFuncSetAttribute(flash_kernel, cudaFuncAttributeMaxDynamicSharedMemorySize,
                         FLASH_SMEM_BYTES);

    prep_a_kernel<<<(PA_TOT * 4 + 255) / 256, 256>>>(W1, b1, W2, b2, W4, b4, W6);
    prep_b_kernel<<<(PB_TOT * 4 + 255) / 256, 256>>>(W1, b1, W2, b2, W3, b3, W5, W6);

    dim3 pgrid(N_TOK / 64, BATCH, 3);
    proj_all_kernel<<<pgrid, 128>>>(
        context, h0, h1, x,
        (const __nv_bfloat16*)pWks, (const float*)pBks,
        (const __nv_bfloat16*)pWv6, (const float*)pBv6,
        (const __nv_bfloat16*)pWq, b5,
        (__nv_bfloat16*)pKsum, (__half*)pV6, (__nv_bfloat16*)pQ);

    dim3 fgrid(N_TOK / QT, BATCH);
    flash_kernel<<<fgrid, 256, FLASH_SMEM_BYTES>>>(
        (const __nv_bfloat16*)pQ, (const __nv_bfloat16*)pKsum,
        (const __half*)pV6, b6, x, out);
}

// round 12
// speedup vs baseline: 2.1423x; 1.0110x over previous
#include <cuda_runtime.h>
#include <cuda_bf16.h>
#include <cuda_fp16.h>
#include <cstdint>

// Problem constants (fixed shapes)
#define N_TOK 8192     // D*H*W
#define BATCH 2
#define CC 96
#define CV 288
#define KIN 320

// ---------------------------------------------------------------------------
// Device scratch
// ---------------------------------------------------------------------------
__device__ float g_W64[CC * CV];     // W6 @ W4  (fp32, stage-A scratch)
__device__ float g_bvc[CV];          // combined v bias (fp32, stage-A scratch)

__device__ __align__(128) __nv_bfloat16 g_Wks[CC * KIN];
__device__ float         g_bks[CC];
__device__ __align__(128) __nv_bfloat16 g_Wv6[CC * KIN];   // (W6@W4) @ [W1;W2]
__device__ float         g_bv6[CC];
__device__ __align__(128) __nv_bfloat16 g_Wq[CC * CC];
__device__ __align__(128) __nv_bfloat16 g_ksum[(size_t)BATCH * N_TOK * CC];  // [B,N,96] bf16 (log2e)
__device__ __align__(128) __nv_bfloat16 g_q[(size_t)BATCH * N_TOK * CC];     // [B,N,96] bf16
__device__ __align__(128) __half        g_v6[(size_t)BATCH * CC * N_TOK];    // [B,96,N] fp16

// ---------------------------------------------------------------------------
// Helpers
// ---------------------------------------------------------------------------
__device__ __forceinline__ uint32_t ld32bf(const __nv_bfloat16* p) {
    return *reinterpret_cast<const uint32_t*>(p);
}

__device__ __forceinline__ void mma_bf16(float& d0, float& d1, float& d2, float& d3,
                                         uint32_t a0, uint32_t a1, uint32_t a2, uint32_t a3,
                                         uint32_t b0, uint32_t b1)
{
    asm volatile(
        "mma.sync.aligned.m16n8k16.row.col.f32.bf16.bf16.f32 "
        "{%0,%1,%2,%3}, {%4,%5,%6,%7}, {%8,%9}, {%0,%1,%2,%3};\n"
        : "+f"(d0), "+f"(d1), "+f"(d2), "+f"(d3)
        : "r"(a0), "r"(a1), "r"(a2), "r"(a3), "r"(b0), "r"(b1));
}

__device__ __forceinline__ void mma_f16(float& d0, float& d1, float& d2, float& d3,
                                        uint32_t a0, uint32_t a1, uint32_t a2, uint32_t a3,
                                        uint32_t b0, uint32_t b1)
{
    asm volatile(
        "mma.sync.aligned.m16n8k16.row.col.f32.f16.f16.f32 "
        "{%0,%1,%2,%3}, {%4,%5,%6,%7}, {%8,%9}, {%0,%1,%2,%3};\n"
        : "+f"(d0), "+f"(d1), "+f"(d2), "+f"(d3)
        : "r"(a0), "r"(a1), "r"(a2), "r"(a3), "r"(b0), "r"(b1));
}

__device__ __forceinline__ void ldsm4(uint32_t addr, uint32_t& r0, uint32_t& r1,
                                      uint32_t& r2, uint32_t& r3)
{
    asm volatile("ldmatrix.sync.aligned.m8n8.x4.shared.b16 {%0,%1,%2,%3}, [%4];\n"
                 : "=r"(r0), "=r"(r1), "=r"(r2), "=r"(r3) : "r"(addr));
}

__device__ __forceinline__ void cp16(uint32_t smem_dst, const void* gsrc)
{
    asm volatile("cp.async.cg.shared.global [%0], [%1], 16;\n"
                 :: "r"(smem_dst), "l"(gsrc));
}
__device__ __forceinline__ void cp_commit() { asm volatile("cp.async.commit_group;\n"); }
__device__ __forceinline__ void cp_wait0()  { asm volatile("cp.async.wait_group 0;\n"); }

// exp2 on two packed fp16; inputs fp32 (log2 domain), output f16x2 bits
__device__ __forceinline__ uint32_t ex2_f16x2(float a, float b)
{
    __half2 h = __floats2half2_rn(a, b);
    uint32_t hin = *reinterpret_cast<uint32_t*>(&h);
    uint32_t r;
    asm("ex2.approx.f16x2 %0, %1;" : "=r"(r) : "r"(hin));
    return r;
}

// ---------------------------------------------------------------------------
// Prep stage A: W64 = W6 @ W4, bvc = b4 + W4a@b1 + W4b@b2
// 4 threads per output, quad-shfl reduce.
// ---------------------------------------------------------------------------
#define PA_TOT (CC * CV + CV)

__global__ void __launch_bounds__(256) prep_a_kernel(
    const float* __restrict__ W1, const float* __restrict__ b1,
    const float* __restrict__ W2, const float* __restrict__ b2,
    const float* __restrict__ W4, const float* __restrict__ b4,
    const float* __restrict__ W6)
{
    int t = blockIdx.x * blockDim.x + threadIdx.x;
    int e = t >> 2;
    int q = t & 3;
    if (e >= PA_TOT) return;
    const uint32_t qmask = 0xFu << (threadIdx.x & 28);

    float acc = 0.f;
    if (e < CC * CV) {
        int o = e / CV, j = e % CV;
        const float* w6 = W6 + o * CV;
        #pragma unroll 4
        for (int c = 72 * q; c < 72 * q + 72; c++) acc += w6[c] * W4[c * CV + j];
        acc += __shfl_xor_sync(qmask, acc, 1);
        acc += __shfl_xor_sync(qmask, acc, 2);
        if (q == 0) g_W64[e] = acc;
    } else {
        int c = e - CC * CV;
        const float* w4 = W4 + c * CV;
        if (q == 0) acc += b4[c];
        for (int j = 48 * q; j < 48 * q + 48; j++) acc += w4[j] * b1[j];
        for (int j = 24 * q; j < 24 * q + 24; j++) acc += w4[192 + j] * b2[j];
        acc += __shfl_xor_sync(qmask, acc, 1);
        acc += __shfl_xor_sync(qmask, acc, 2);
        if (q == 0) g_bvc[c] = acc;
    }
}

// ---------------------------------------------------------------------------
// Prep stage B: Wks (log2e), bks, Wv6 = W64 @ [W1;W2], bv6 = W6 @ bvc, Wq
// ---------------------------------------------------------------------------
#define PB_O_WKS 0
#define PB_O_BKS (CC * KIN)                  // 30720
#define PB_O_WV6 (PB_O_BKS + CC)             // 30816
#define PB_O_BV6 (PB_O_WV6 + CC * KIN)       // 61536
#define PB_O_WQ  (PB_O_BV6 + CC)             // 61632
#define PB_TOT   (PB_O_WQ + CC * CC)         // 70848

__global__ void __launch_bounds__(256) prep_b_kernel(
    const float* __restrict__ W1, const float* __restrict__ b1,
    const float* __restrict__ W2, const float* __restrict__ b2,
    const float* __restrict__ W3, const float* __restrict__ b3,
    const float* __restrict__ W5, const float* __restrict__ W6)
{
    const float LOG2E = 1.44269504088896341f;
    int t = blockIdx.x * blockDim.x + threadIdx.x;
    int e = t >> 2;
    int q = t & 3;
    if (e >= PB_TOT) return;
    const uint32_t qmask = 0xFu << (threadIdx.x & 28);

    float acc = 0.f;

    if (e < PB_O_BKS) {
        int c = e / KIN, i = e % KIN;
        if (i < 128) {
            #pragma unroll 1
            for (int r = 0; r < 3; r++) {
                const float* w3 = W3 + (c + 96 * r) * 288;
                #pragma unroll 4
                for (int j = 48 * q; j < 48 * q + 48; j++) acc += w3[j] * W1[j * 128 + i];
            }
        } else {
            int ih = i - 128;
            #pragma unroll 1
            for (int r = 0; r < 3; r++) {
                const float* w3 = W3 + (c + 96 * r) * 288 + 192;
                #pragma unroll 4
                for (int j = 24 * q; j < 24 * q + 24; j++) acc += w3[j] * W2[j * 192 + ih];
            }
        }
        acc += __shfl_xor_sync(qmask, acc, 1);
        acc += __shfl_xor_sync(qmask, acc, 2);
        if (q == 0) g_Wks[e] = __float2bfloat16(acc * LOG2E);
    } else if (e < PB_O_WV6) {
        int c = e - PB_O_BKS;
        #pragma unroll 1
        for (int r = 0; r < 3; r++) {
            int row = c + 96 * r;
            if (q == 0) acc += b3[row];
            const float* w3 = W3 + row * 288;
            for (int j = 48 * q; j < 48 * q + 48; j++) acc += w3[j] * b1[j];
            for (int j = 24 * q; j < 24 * q + 24; j++) acc += w3[192 + j] * b2[j];
        }
        acc += __shfl_xor_sync(qmask, acc, 1);
        acc += __shfl_xor_sync(qmask, acc, 2);
        if (q == 0) g_bks[c] = acc * LOG2E;
    } else if (e < PB_O_BV6) {
        int u = e - PB_O_WV6;
        int o = u / KIN, i = u % KIN;
        if (i < 128) {
            const float* w = g_W64 + o * CV;
            #pragma unroll 4
            for (int j = 48 * q; j < 48 * q + 48; j++) acc += w[j] * W1[j * 128 + i];
        } else {
            int ih = i - 128;
            const float* w = g_W64 + o * CV + 192;
            #pragma unroll 4
            for (int j = 24 * q; j < 24 * q + 24; j++) acc += w[j] * W2[j * 192 + ih];
        }
        acc += __shfl_xor_sync(qmask, acc, 1);
        acc += __shfl_xor_sync(qmask, acc, 2);
        if (q == 0) g_Wv6[u] = __float2bfloat16(acc);
    } else if (e < PB_O_WQ) {
        int o = e - PB_O_BV6;
        const float* w6 = W6 + o * CV;
        #pragma unroll 4
        for (int c = 72 * q; c < 72 * q + 72; c++) acc += w6[c] * g_bvc[c];
        acc += __shfl_xor_sync(qmask, acc, 1);
        acc += __shfl_xor_sync(qmask, acc, 2);
        if (q == 0) g_bv6[o] = acc;
    } else {
        if (q == 0) {
            int u = e - PB_O_WQ;
            g_Wq[u] = __float2bfloat16(W5[u]);
        }
    }
}

// ---------------------------------------------------------------------------
// Projection GEMM body. OUTMODE: 0 = bf16 tok-major [B,N,M], 1 = fp16 ch-major [B,M,N]
// ---------------------------------------------------------------------------
template<int M, int K, int OUTMODE>
__device__ __forceinline__ void proj_body(
    const float* __restrict__ s0, int k0,
    const float* __restrict__ s1, int k1,
    const float* __restrict__ s2,
    const __nv_bfloat16* __restrict__ W,
    const float* __restrict__ bias,
    void* __restrict__ outv,
    __nv_bfloat16* sX)
{
    const int tid = threadIdx.x;
    const int warp = tid >> 5;
    const int lane = tid & 31;
    const int t4 = lane >> 2;
    const int tm4 = lane & 3;
    const int b = blockIdx.y;
    const int n0 = blockIdx.x * 64;
    const int rw = warp * 16;

    const float* p0 = s0 + (size_t)b * k0 * N_TOK;
    const float* p1 = s1 + (size_t)b * k1 * N_TOK;
    const float* p2 = s2 + (size_t)b * (K - k0 - k1) * N_TOK;

    constexpr int MT = M / 8;
    float acc[MT][4];
    #pragma unroll
    for (int i = 0; i < MT; i++) { acc[i][0]=0.f; acc[i][1]=0.f; acc[i][2]=0.f; acc[i][3]=0.f; }

    for (int kc = 0; kc < K; kc += 32) {
        #pragma unroll
        for (int it = 0; it < 16; it++) {
            int idx = it * 128 + tid;
            int k = idx >> 6;
            int n = idx & 63;
            int r = kc + k;
            float v;
            if (r < k0)            v = p0[(size_t)r * N_TOK + n0 + n];
            else if (r < k0 + k1)  v = p1[(size_t)(r - k0) * N_TOK + n0 + n];
            else                   v = p2[(size_t)(r - k0 - k1) * N_TOK + n0 + n];
            sX[n * 40 + k] = __float2bfloat16(v);
        }
        __syncthreads();

        #pragma unroll
        for (int ks = 0; ks < 2; ks++) {
            const __nv_bfloat16* qb = sX + (rw + t4) * 40 + ks * 16 + 2 * tm4;
            uint32_t a0 = ld32bf(qb);
            uint32_t a1 = ld32bf(qb + 8 * 40);
            uint32_t a2 = ld32bf(qb + 8);
            uint32_t a3 = ld32bf(qb + 8 * 40 + 8);
            #pragma unroll
            for (int mt = 0; mt < MT; mt++) {
                const __nv_bfloat16* wb = W + (size_t)(mt * 8 + t4) * K + kc + ks * 16 + 2 * tm4;
                uint32_t b0 = ld32bf(wb);
                uint32_t b1 = ld32bf(wb + 8);
                mma_bf16(acc[mt][0], acc[mt][1], acc[mt][2], acc[mt][3],
                         a0, a1, a2, a3, b0, b1);
            }
        }
        __syncthreads();
    }

    int row0 = n0 + rw + t4;
    #pragma unroll
    for (int mt = 0; mt < MT; mt++) {
        int o = mt * 8 + 2 * tm4;
        float bz0 = bias[o], bz1 = bias[o + 1];
        float v0 = acc[mt][0] + bz0;
        float v1 = acc[mt][1] + bz1;
        float v2 = acc[mt][2] + bz0;
        float v3 = acc[mt][3] + bz1;
        if (OUTMODE == 0) {
            __nv_bfloat16* out = (__nv_bfloat16*)outv;
            *reinterpret_cast<__nv_bfloat162*>(out + ((size_t)(b * N_TOK + row0)) * M + o) =
                __floats2bfloat162_rn(v0, v1);
            *reinterpret_cast<__nv_bfloat162*>(out + ((size_t)(b * N_TOK + row0 + 8)) * M + o) =
                __floats2bfloat162_rn(v2, v3);
        } else {
            __half* out = (__half*)outv;
            out[((size_t)(b * M + o)) * N_TOK + row0]         = __float2half(v0);
            out[((size_t)(b * M + o + 1)) * N_TOK + row0]     = __float2half(v1);
            out[((size_t)(b * M + o)) * N_TOK + row0 + 8]     = __float2half(v2);
            out[((size_t)(b * M + o + 1)) * N_TOK + row0 + 8] = __float2half(v3);
        }
    }
}

// Merged projection kernel: z=0 ksum, z=1 v6 (fp16 ch-major), z=2 q.
__global__ void __launch_bounds__(128) proj_all_kernel(
    const float* __restrict__ context, const float* __restrict__ h0,
    const float* __restrict__ h1, const float* __restrict__ x,
    const __nv_bfloat16* __restrict__ Wks, const float* __restrict__ bks,
    const __nv_bfloat16* __restrict__ Wv6, const float* __restrict__ bv6,
    const __nv_bfloat16* __restrict__ Wq, const float* __restrict__ b5,
    __nv_bfloat16* __restrict__ ksum_out, __half* __restrict__ v6_out,
    __nv_bfloat16* __restrict__ q_out)
{
    __shared__ __nv_bfloat16 sX[64 * 40];
    int z = blockIdx.z;
    if (z == 0) {
        proj_body<CC, KIN, 0>(context, 128, h0, 96, h1, Wks, bks, ksum_out, sX);
    } else if (z == 1) {
        proj_body<CC, KIN, 1>(context, 128, h0, 96, h1, Wv6, bv6, v6_out, sX);
    } else {
        proj_body<CC, CC, 0>(x, 96, x, 0, x, Wq, b5, q_out, sX);
    }
}

// ---------------------------------------------------------------------------
// Flash attention with pre-projected V6 (96 channels).
//   R6-proven structure: 8 warps x 16 Q rows, KV tiles 64, double-buffered
//   cp.async, bf16 QK, fp16 P/V6, ex2.f16x2 softmax, no mid-iter syncs.
//   Epilogue: out = O/l + b6 + x directly (no W6 GEMM - folded into V6).
// smem: sQ[128][104] @0 (26,624) | K bufs 2x[64][104] @26,624 (2x13,312)
//       V6 bufs 2x[96][72] fp16 @53,248 (2x13,824) -> total 80,896 B
// ---------------------------------------------------------------------------
#define QT 128
#define KT 64
#define NIT (N_TOK / KT)
#define SQ_ELEMS (128 * 104)
#define SK_ELEMS (64 * 104)
#define SV_ELEMS (96 * 72)
#define FLASH_SMEM_BYTES ((SQ_ELEMS + 2 * SK_ELEMS + 2 * SV_ELEMS) * 2)  // 80,896

__global__ void __launch_bounds__(256, 1) flash_kernel(
    const __nv_bfloat16* __restrict__ qt,    // [B, N, 96]
    const __nv_bfloat16* __restrict__ kst,   // [B, N, 96] (log2e-scaled)
    const __half* __restrict__ v6,           // [B, 96, N] fp16
    const float* __restrict__ b6,
    const float* __restrict__ x,             // [B, 96, N]
    float* __restrict__ out)                 // [B, 96, N]
{
    extern __shared__ __nv_bfloat16 smem[];
    __nv_bfloat16* sQ = smem;

    const int tid = threadIdx.x;
    const int warp = tid >> 5;
    const int lane = tid & 31;
    const int t4 = lane >> 2;
    const int tm4 = lane & 3;
    const int b = blockIdx.y;
    const int n0 = blockIdx.x * QT;
    const int rw = warp * 16;

    const uint32_t smem_b = (uint32_t)__cvta_generic_to_shared(smem);
    const uint32_t sQ_b = smem_b;
    const uint32_t sK_b = smem_b + SQ_ELEMS * 2;
    const uint32_t sV_b = smem_b + (SQ_ELEMS + 2 * SK_ELEMS) * 2;

    const int lg = lane >> 3;
    const int lr = lane & 7;
    const int rsel = (lg & 1) * 8 + lr;
    const int csel = (lg >> 1) * 8;
    const uint32_t aAddr0 = sQ_b + ((rw + rsel) * 104 + csel) * 2;
    const uint32_t kAddr0 = sK_b + (rsel * 104 + csel) * 2;
    const uint32_t vAddr0 = sV_b + (rsel * 72 + csel) * 2;

    // ---- load Q tile ----
    {
        const __nv_bfloat16* qsrc = qt + ((size_t)(b * N_TOK + n0)) * 96;
        #pragma unroll
        for (int it = 0; it < 6; it++) {
            int idx = it * 256 + tid;
            int row = idx / 12;
            int c8 = idx % 12;
            *reinterpret_cast<uint4*>(sQ + row * 104 + c8 * 8) =
                *reinterpret_cast<const uint4*>(qsrc + (size_t)row * 96 + c8 * 8);
        }
    }

    // ---- async tile loader ----
    const __nv_bfloat16* kbase = kst + ((size_t)b * N_TOK) * 96;
    const __half* vbase = v6 + ((size_t)b * CC) * N_TOK;
    auto issue_tile = [&](int mt_i, int buf) {
        const int m0 = mt_i * KT;
        // K tile: 64 rows x 96 cols = 768 16B chunks
        #pragma unroll
        for (int it = 0; it < 3; it++) {
            int c = it * 256 + tid;
            int row = c / 12, col = c % 12;
            cp16(sK_b + (buf * SK_ELEMS + row * 104 + col * 8) * 2,
                 kbase + (size_t)(m0 + row) * 96 + col * 8);
        }
        // V6 tile: 96 rows x 64 cols = 768 16B chunks
        #pragma unroll
        for (int it = 0; it < 3; it++) {
            int c = it * 256 + tid;
            int row = c >> 3, col = c & 7;
            cp16(sV_b + (buf * SV_ELEMS + row * 72 + col * 8) * 2,
                 vbase + (size_t)row * N_TOK + m0 + col * 8);
        }
        cp_commit();
    };

    float o_[12][4];
    #pragma unroll
    for (int i = 0; i < 12; i++) { o_[i][0]=0.f; o_[i][1]=0.f; o_[i][2]=0.f; o_[i][3]=0.f; }
    float l0 = 0.f, l1 = 0.f;

    issue_tile(0, 0);

    int buf = 0;
    for (int mt_i = 0; mt_i < NIT; mt_i++) {
        cp_wait0();
        __syncthreads();
        if (mt_i + 1 < NIT) issue_tile(mt_i + 1, buf ^ 1);

        const uint32_t kB = kAddr0 + buf * (SK_ELEMS * 2);
        const uint32_t vB = vAddr0 + buf * (SV_ELEMS * 2);

        // ---- S = Q @ K^T (bf16) ----
        float s[8][4];
        #pragma unroll
        for (int j = 0; j < 8; j++) { s[j][0]=0.f; s[j][1]=0.f; s[j][2]=0.f; s[j][3]=0.f; }
        #pragma unroll
        for (int kk = 0; kk < 6; kk++) {
            uint32_t a0, a1, a2, a3;
            ldsm4(aAddr0 + kk * 32, a0, a1, a2, a3);
            #pragma unroll
            for (int jj = 0; jj < 4; jj++) {
                uint32_t b00, b01, b10, b11;
                ldsm4(kB + jj * (16 * 208) + kk * 32, b00, b01, b10, b11);
                mma_bf16(s[2*jj][0], s[2*jj][1], s[2*jj][2], s[2*jj][3],
                         a0, a1, a2, a3, b00, b10);
                mma_bf16(s[2*jj+1][0], s[2*jj+1][1], s[2*jj+1][2], s[2*jj+1][3],
                         a0, a1, a2, a3, b01, b11);
            }
        }

        // ---- P = exp2(S) via f16x2 MUFU; fp32 row sums; P fp16 in regs ----
        uint32_t pa[4][4];
        #pragma unroll
        for (int j = 0; j < 8; j++) {
            uint32_t e01 = ex2_f16x2(s[j][0], s[j][1]);
            uint32_t e23 = ex2_f16x2(s[j][2], s[j][3]);
            float2 f01 = __half22float2(*reinterpret_cast<__half2*>(&e01));
            float2 f23 = __half22float2(*reinterpret_cast<__half2*>(&e23));
            l0 += f01.x + f01.y;
            l1 += f23.x + f23.y;
            pa[j >> 1][(j & 1) * 2]     = e01;
            pa[j >> 1][(j & 1) * 2 + 1] = e23;
        }

        // ---- O += P @ V6^T (fp16 inputs, fp32 accum; 96 channels) ----
        #pragma unroll
        for (int g = 0; g < 4; g++) {
            #pragma unroll
            for (int cc = 0; cc < 6; cc++) {
                uint32_t r0, r1, r2, r3;
                ldsm4(vB + cc * (16 * 144) + g * 32, r0, r1, r2, r3);
                mma_f16(o_[2*cc][0], o_[2*cc][1], o_[2*cc][2], o_[2*cc][3],
                        pa[g][0], pa[g][1], pa[g][2], pa[g][3], r0, r2);
                mma_f16(o_[2*cc+1][0], o_[2*cc+1][1], o_[2*cc+1][2], o_[2*cc+1][3],
                        pa[g][0], pa[g][1], pa[g][2], pa[g][3], r1, r3);
            }
        }
        buf ^= 1;
        __syncthreads();
    }

    // ---- finalize softmax normalization ----
    l0 += __shfl_xor_sync(0xffffffffu, l0, 1);
    l0 += __shfl_xor_sync(0xffffffffu, l0, 2);
    l1 += __shfl_xor_sync(0xffffffffu, l1, 1);
    l1 += __shfl_xor_sync(0xffffffffu, l1, 2);
    float inv0 = 1.f / l0;
    float inv1 = 1.f / l1;

    // ---- epilogue: out = O/l + b6 + x (W6 already folded into V6) ----
    int n = n0 + rw + t4;
    #pragma unroll
    for (int mt = 0; mt < 12; mt++) {
        int o = mt * 8 + 2 * tm4;
        size_t i00 = ((size_t)(b * CC + o)) * N_TOK + n;
        size_t i01 = i00 + N_TOK;
        out[i00]     = o_[mt][0] * inv0 + b6[o]     + x[i00];
        out[i01]     = o_[mt][1] * inv0 + b6[o + 1] + x[i01];
        out[i00 + 8] = o_[mt][2] * inv1 + b6[o]     + x[i00 + 8];
        out[i01 + 8] = o_[mt][3] * inv1 + b6[o + 1] + x[i01 + 8];
    }
}

// ---------------------------------------------------------------------------
// Launch
// ---------------------------------------------------------------------------
extern "C" void kernel_launch(void* const* d_in, const int* in_sizes, int n_in,
                              void* d_out, int out_size)
{
    const float* context = (const float*)d_in[0];
    const float* h0 = (const float*)d_in[1];
    const float* h1 = (const float*)d_in[2];
    const float* x  = (const float*)d_in[3];
    const float* W1 = (const float*)d_in[4];
    const float* b1 = (const float*)d_in[5];
    const float* W2 = (const float*)d_in[6];
    const float* b2 = (const float*)d_in[7];
    const float* W3 = (const float*)d_in[8];
    const float* b3 = (const float*)d_in[9];
    const float* W4 = (const float*)d_in[10];
    const float* b4 = (const float*)d_in[11];
    const float* W5 = (const float*)d_in[12];
    const float* b5 = (const float*)d_in[13];
    const float* W6 = (const float*)d_in[14];
    const float* b6 = (const float*)d_in[15];
    float* out = (float*)d_out;

    void *pWks, *pBks, *pWv6, *pBv6, *pWq, *pKsum, *pQ, *pV6;
    cudaGetSymbolAddress(&pWks, g_Wks);
    cudaGetSymbolAddress(&pBks, g_bks);
    cudaGetSymbolAddress(&pWv6, g_Wv6);
    cudaGetSymbolAddress(&pBv6, g_bv6);
    cudaGetSymbolAddress(&pWq, g_Wq);
    cudaGetSymbolAddress(&pKsum, g_ksum);
    cudaGetSymbolAddress(&pQ, g_q);
    cudaGetSymbolAddress(&pV6, g_v6);

    cudaFuncSetAttribute(flash_kernel, cudaFuncAttributeMaxDynamicSharedMemorySize,
                         FLASH_SMEM_BYTES);

    prep_a_kernel<<<(PA_TOT * 4 + 255) / 256, 256>>>(W1, b1, W2, b2, W4, b4, W6);
    prep_b_kernel<<<(PB_TOT * 4 + 255) / 256, 256>>>(W1, b1, W2, b2, W3, b3, W5, W6);

    dim3 pgrid(N_TOK / 64, BATCH, 3);
    proj_all_kernel<<<pgrid, 128>>>(
        context, h0, h1, x,
        (const __nv_bfloat16*)pWks, (const float*)pBks,
        (const __nv_bfloat16*)pWv6, (const float*)pBv6,
        (const __nv_bfloat16*)pWq, b5,
        (__nv_bfloat16*)pKsum, (__half*)pV6, (__nv_bfloat16*)pQ);

    dim3 fgrid(N_TOK / QT, BATCH);
    flash_kernel<<<fgrid, 256, FLASH_SMEM_BYTES>>>(
        (const __nv_bfloat16*)pQ, (const __nv_bfloat16*)pKsum,
        (const __half*)pV6, b6, x, out);
}